// round 3
// baseline (speedup 1.0000x reference)
#include <cuda_runtime.h>
#include <cuda_bf16.h>
#include <cstdint>

// ---------------------------------------------------------------------------
// Mamba2 layer (B=4, L=2048, d_model=512, d_inner=1024, d_state=128, nheads=1)
// Pipeline: GEMM(in-proj) -> dt prep -> depthwise conv+silu -> selective scan
//           -> gated RMSNorm -> GEMM(out-proj) -> copy rnn_state passthrough
// All fp32, inner loops in packed fma.rn.f32x2 (2 FMA lanes / instr on sm_103a).
// ---------------------------------------------------------------------------

typedef unsigned long long ull;

#define BATCH   4
#define SEQ     2048
#define TOK     (BATCH * SEQ)        // 8192
#define DMODEL  512
#define DINNER  1024
#define DSTATE  128
#define DPROJ   2305                 // 2*1024 + 2*128 + 1
#define CONVCH  1280                 // 1024 + 256

// scratch (static __device__ arrays; no cudaMalloc allowed)
__device__ float g_proj [(size_t)TOK * DPROJ];    // 75.5 MB
__device__ float g_xconv[(size_t)TOK * CONVCH];   // 41.9 MB
__device__ float g_dt   [TOK];
__device__ float g_dA   [TOK];
__device__ float g_yraw [(size_t)TOK * DINNER];   // 33.5 MB
__device__ float g_ynorm[(size_t)TOK * DINNER];   // 33.5 MB

// ---------------- packed f32x2 helpers ----------------
__device__ __forceinline__ ull pk(float lo, float hi) {
    ull r; asm("mov.b64 %0, {%1, %2};" : "=l"(r) : "f"(lo), "f"(hi)); return r;
}
__device__ __forceinline__ float2 unpk(ull v) {
    float2 r; asm("mov.b64 {%0, %1}, %2;" : "=f"(r.x), "=f"(r.y) : "l"(v)); return r;
}
__device__ __forceinline__ ull fma2(ull a, ull b, ull c) {
    ull d; asm("fma.rn.f32x2 %0, %1, %2, %3;" : "=l"(d) : "l"(a), "l"(b), "l"(c)); return d;
}
__device__ __forceinline__ ull mul2(ull a, ull b) {
    ull d; asm("mul.rn.f32x2 %0, %1, %2;" : "=l"(d) : "l"(a), "l"(b)); return d;
}

// ---------------------------------------------------------------------------
// Generic fp32 GEMM:  C[M,N] = A[M,K] * B[N,K]^T   (both K-major / row-major)
// 128x128 block tile, 32 K-tile, 256 threads, 8x8 per thread, packed f32x2.
// Requires: M % 128 == 0, K % 32 == 0, 16B-aligned A/B rows (K % 4 == 0).
// ---------------------------------------------------------------------------
__global__ void __launch_bounds__(256, 2)
gemm_nt(const float* __restrict__ A, const float* __restrict__ B,
        float* __restrict__ C, int M, int N, int K)
{
    __shared__ __align__(16) float As[32][132];
    __shared__ __align__(16) float Bs[32][132];

    const int tid = threadIdx.x;
    const int tx  = tid & 15;          // 0..15 -> N
    const int ty  = tid >> 4;          // 0..15 -> M
    const int mb  = blockIdx.y * 128;
    const int nb  = blockIdx.x * 128;

    ull acc[8][4];
#pragma unroll
    for (int i = 0; i < 8; i++)
#pragma unroll
        for (int j = 0; j < 4; j++) acc[i][j] = 0ull;

    for (int k0 = 0; k0 < K; k0 += 32) {
#pragma unroll
        for (int r = 0; r < 4; r++) {
            const int q  = tid + r * 256;      // 0..1023
            const int m  = q >> 3;             // 0..127
            const int kq = q & 7;              // 0..7 (float4 chunks of 32 k)
            // A tile (rows always in-bounds: M multiple of 128, grid exact)
            const float4 va = *(const float4*)(A + (size_t)(mb + m) * K + k0 + kq * 4);
            As[kq * 4 + 0][m] = va.x;
            As[kq * 4 + 1][m] = va.y;
            As[kq * 4 + 2][m] = va.z;
            As[kq * 4 + 3][m] = va.w;
            // B tile (N may be ragged: 2305)
            float4 vb = make_float4(0.f, 0.f, 0.f, 0.f);
            const int gn = nb + m;
            if (gn < N)
                vb = *(const float4*)(B + (size_t)gn * K + k0 + kq * 4);
            Bs[kq * 4 + 0][m] = vb.x;
            Bs[kq * 4 + 1][m] = vb.y;
            Bs[kq * 4 + 2][m] = vb.z;
            Bs[kq * 4 + 3][m] = vb.w;
        }
        __syncthreads();

#pragma unroll
        for (int k = 0; k < 32; k++) {
            const float4 a0 = *(const float4*)&As[k][ty * 8];
            const float4 a1 = *(const float4*)&As[k][ty * 8 + 4];
            const ulonglong2 b01 = *(const ulonglong2*)&Bs[k][tx * 8];
            const ulonglong2 b23 = *(const ulonglong2*)&Bs[k][tx * 8 + 4];
            ull bv[4] = { b01.x, b01.y, b23.x, b23.y };
            ull ad[8] = { pk(a0.x, a0.x), pk(a0.y, a0.y), pk(a0.z, a0.z), pk(a0.w, a0.w),
                          pk(a1.x, a1.x), pk(a1.y, a1.y), pk(a1.z, a1.z), pk(a1.w, a1.w) };
#pragma unroll
            for (int i = 0; i < 8; i++)
#pragma unroll
                for (int j = 0; j < 4; j++)
                    acc[i][j] = fma2(ad[i], bv[j], acc[i][j]);
        }
        __syncthreads();
    }

#pragma unroll
    for (int i = 0; i < 8; i++) {
        const size_t row = (size_t)(mb + ty * 8 + i) * N;
#pragma unroll
        for (int j = 0; j < 4; j++) {
            const float2 v = unpk(acc[i][j]);
            const int gn = nb + tx * 8 + j * 2;
            if (gn     < N) C[row + gn]     = v.x;
            if (gn + 1 < N) C[row + gn + 1] = v.y;
        }
    }
}

// ---------------------------------------------------------------------------
// dt = softplus(proj[:,2304] + dt_bias); dA = exp(dt * (-exp(A_log)))
// ---------------------------------------------------------------------------
__global__ void dtprep(const float* __restrict__ proj,
                       const float* __restrict__ dt_bias,
                       const float* __restrict__ A_log,
                       float* __restrict__ gdt, float* __restrict__ gdA)
{
    const int t = blockIdx.x * blockDim.x + threadIdx.x;
    if (t >= TOK) return;
    const float raw = proj[(size_t)t * DPROJ + (DPROJ - 1)] + dt_bias[0];
    const float dt  = (raw > 20.f) ? raw : log1pf(expf(raw));
    const float A   = -expf(A_log[0]);
    gdt[t] = dt;
    gdA[t] = expf(dt * A);
}

// ---------------------------------------------------------------------------
// causal depthwise conv1d (width 4) + bias + silu over the 1280 xBC channels
// out[t,c] layout: [TOK][1280]
// ---------------------------------------------------------------------------
__global__ void conv_silu(const float* __restrict__ proj,
                          const float* __restrict__ cw,   // (1280,1,4)
                          const float* __restrict__ cb,
                          float* __restrict__ xconv)
{
    const int id = blockIdx.x * 256 + threadIdx.x;
    if (id >= TOK * CONVCH) return;
    const int c   = id % CONVCH;
    const int tkn = id / CONVCH;
    const int l   = tkn & (SEQ - 1);

    const float4 w = ((const float4*)cw)[c];      // w.x..w.w = taps k=0..3
    const float* col = proj + (size_t)tkn * DPROJ + DINNER + c;

    float acc = cb[c];
    acc += col[0] * w.w;                          // k=3 -> in[l]
    if (l >= 1) acc += *(col - (size_t)DPROJ)     * w.z;
    if (l >= 2) acc += *(col - (size_t)2 * DPROJ) * w.y;
    if (l >= 3) acc += *(col - (size_t)3 * DPROJ) * w.x;

    acc = acc / (1.f + expf(-acc));               // silu
    xconv[(size_t)tkn * CONVCH + c] = acc;
}

// ---------------------------------------------------------------------------
// Selective scan. Grid (32 p-tiles, 4 batches), 128 threads.
// Thread owns 2 p x 16 n (32 fp32 state as 16 packed f32x2). 8 threads per p.
// B_t/C_t/x_t staged through double-buffered smem; one barrier per step.
// yraw[t,p] = (state_t[p,:] . C_t) + Dp * x_t[p]
// ---------------------------------------------------------------------------
__global__ void __launch_bounds__(128)
scan_kernel(const float* __restrict__ xconv,
            const float* __restrict__ dts,
            const float* __restrict__ dAs,
            const float* __restrict__ Dp,
            float* __restrict__ yraw)
{
    const int b      = blockIdx.y;
    const int pbase  = blockIdx.x * 32;
    const int tid    = threadIdx.x;
    const int nslice = tid & 7;       // 8 slices of 16 n
    const int pair   = tid >> 3;      // 0..15 -> p pair
    const int p0     = pbase + pair * 2;

    __shared__ __align__(16) float sB[2][DSTATE];
    __shared__ __align__(16) float sC[2][DSTATE];
    __shared__ __align__(16) float sX[2][32];
    __shared__ float sS[2][2];        // dt, dA

    ull st0[8], st1[8];
#pragma unroll
    for (int i = 0; i < 8; i++) { st0[i] = 0ull; st1[i] = 0ull; }

    const float dval = Dp[0];

    auto load_step = [&](int t, int buf) {
        const float* base = xconv + (size_t)(b * SEQ + t) * CONVCH;
        if (tid < 32) {
            *(float4*)&sB[buf][tid * 4] = *(const float4*)(base + DINNER + tid * 4);
        } else if (tid < 64) {
            const int j = tid - 32;
            *(float4*)&sC[buf][j * 4] = *(const float4*)(base + DINNER + DSTATE + j * 4);
        } else if (tid < 72) {
            const int j = tid - 64;
            *(float4*)&sX[buf][j * 4] = *(const float4*)(base + pbase + j * 4);
        } else if (tid == 72) {
            sS[buf][0] = dts[b * SEQ + t];
        } else if (tid == 73) {
            sS[buf][1] = dAs[b * SEQ + t];
        }
    };

    load_step(0, 0);
    __syncthreads();

    for (int t = 0; t < SEQ; ++t) {
        const int buf = t & 1;
        if (t + 1 < SEQ) load_step(t + 1, buf ^ 1);

        const float dtv = sS[buf][0];
        const float dAv = sS[buf][1];
        const float x0  = sX[buf][pair * 2 + 0];
        const float x1  = sX[buf][pair * 2 + 1];
        const ull u0p = pk(dtv * x0, dtv * x0);
        const ull u1p = pk(dtv * x1, dtv * x1);
        const ull dAp = pk(dAv, dAv);

        const ulonglong2* Bp = (const ulonglong2*)&sB[buf][nslice * 16];
        const ulonglong2* Cp = (const ulonglong2*)&sC[buf][nslice * 16];

        ull acc0 = 0ull, acc1 = 0ull;
#pragma unroll
        for (int q = 0; q < 4; q++) {
            const ulonglong2 Bq = Bp[q];
            const ulonglong2 Cq = Cp[q];
            st0[2 * q]     = fma2(dAp, st0[2 * q],     mul2(u0p, Bq.x));
            st0[2 * q + 1] = fma2(dAp, st0[2 * q + 1], mul2(u0p, Bq.y));
            st1[2 * q]     = fma2(dAp, st1[2 * q],     mul2(u1p, Bq.x));
            st1[2 * q + 1] = fma2(dAp, st1[2 * q + 1], mul2(u1p, Bq.y));
            acc0 = fma2(st0[2 * q],     Cq.x, acc0);
            acc0 = fma2(st0[2 * q + 1], Cq.y, acc0);
            acc1 = fma2(st1[2 * q],     Cq.x, acc1);
            acc1 = fma2(st1[2 * q + 1], Cq.y, acc1);
        }
        const float2 a0 = unpk(acc0);
        const float2 a1 = unpk(acc1);
        float y0 = a0.x + a0.y;
        float y1 = a1.x + a1.y;
#pragma unroll
        for (int m = 1; m < 8; m <<= 1) {
            y0 += __shfl_xor_sync(0xffffffffu, y0, m);
            y1 += __shfl_xor_sync(0xffffffffu, y1, m);
        }
        if (nslice == 0) {
            float* o = yraw + (size_t)(b * SEQ + t) * DINNER + p0;
            o[0] = y0 + dval * x0;
            o[1] = y1 + dval * x1;
        }
        __syncthreads();
    }
}

// ---------------------------------------------------------------------------
// y = yraw * silu(z); y = y * rsqrt(mean(y^2)+eps) * norm_w
// one block per token, 256 threads x 4 channels
// ---------------------------------------------------------------------------
__global__ void gate_norm(const float* __restrict__ yraw,
                          const float* __restrict__ proj,
                          const float* __restrict__ normw,
                          float* __restrict__ ynorm)
{
    const int t   = blockIdx.x;
    const int tid = threadIdx.x;

    float v[4];
    float ss = 0.f;
#pragma unroll
    for (int j = 0; j < 4; j++) {
        const int p = tid + j * 256;
        const float y = yraw[(size_t)t * DINNER + p];
        const float z = proj[(size_t)t * DPROJ + p];
        const float g = z / (1.f + expf(-z));
        const float val = y * g;
        v[j] = val;
        ss += val * val;
    }
#pragma unroll
    for (int m = 16; m; m >>= 1) ss += __shfl_xor_sync(0xffffffffu, ss, m);

    __shared__ float warpsum[8];
    __shared__ float inv_s;
    if ((tid & 31) == 0) warpsum[tid >> 5] = ss;
    __syncthreads();
    if (tid == 0) {
        float s = 0.f;
#pragma unroll
        for (int i = 0; i < 8; i++) s += warpsum[i];
        inv_s = rsqrtf(s * (1.f / DINNER) + 1e-5f);
    }
    __syncthreads();
    const float inv = inv_s;
#pragma unroll
    for (int j = 0; j < 4; j++) {
        const int p = tid + j * 256;
        ynorm[(size_t)t * DINNER + p] = v[j] * inv * normw[p];
    }
}

// ---------------------------------------------------------------------------
extern "C" void kernel_launch(void* const* d_in, const int* in_sizes, int n_in,
                              void* d_out, int out_size)
{
    const float* x       = (const float*)d_in[0];
    const float* rnn     = (const float*)d_in[1];
    const float* W_in    = (const float*)d_in[2];
    const float* conv_w  = (const float*)d_in[3];
    const float* conv_b  = (const float*)d_in[4];
    const float* dt_bias = (const float*)d_in[5];
    const float* A_log   = (const float*)d_in[6];
    const float* Dp      = (const float*)d_in[7];
    const float* norm_w  = (const float*)d_in[8];
    const float* W_out   = (const float*)d_in[9];
    float* out = (float*)d_out;

    float *proj, *xconv, *gdt, *gdA, *yraw, *ynorm;
    cudaGetSymbolAddress((void**)&proj,  g_proj);
    cudaGetSymbolAddress((void**)&xconv, g_xconv);
    cudaGetSymbolAddress((void**)&gdt,   g_dt);
    cudaGetSymbolAddress((void**)&gdA,   g_dA);
    cudaGetSymbolAddress((void**)&yraw,  g_yraw);
    cudaGetSymbolAddress((void**)&ynorm, g_ynorm);

    // 1) in-projection: proj[8192,2305] = x[8192,512] @ W_in[2305,512]^T
    gemm_nt<<<dim3((DPROJ + 127) / 128, TOK / 128), 256>>>(x, W_in, proj, TOK, DPROJ, DMODEL);

    // 2) dt / dA scalars
    dtprep<<<TOK / 256, 256>>>(proj, dt_bias, A_log, gdt, gdA);

    // 3) depthwise conv + silu on xBC channels
    conv_silu<<<(TOK * CONVCH + 255) / 256, 256>>>(proj, conv_w, conv_b, xconv);

    // 4) selective scan
    scan_kernel<<<dim3(32, BATCH), 128>>>(xconv, gdt, gdA, Dp, yraw);

    // 5) gate + RMSNorm
    gate_norm<<<TOK, 256>>>(yraw, proj, norm_w, ynorm);

    // 6) out-projection: out[8192,512] = ynorm[8192,1024] @ W_out[512,1024]^T
    gemm_nt<<<dim3(DMODEL / 128, TOK / 128), 256>>>(ynorm, W_out, out, TOK, DMODEL, DINNER);

    // 7) rnn_state passthrough (second tuple output)
    const int main_elems = TOK * DMODEL;
    if (out_size >= main_elems + BATCH * DMODEL) {
        cudaMemcpyAsync(out + main_elems, rnn, (size_t)BATCH * DMODEL * sizeof(float),
                        cudaMemcpyDeviceToDevice, 0);
    }
}

// round 6
// speedup vs baseline: 1.4871x; 1.4871x over previous
#include <cuda_runtime.h>
#include <cuda_bf16.h>
#include <cstdint>

// ---------------------------------------------------------------------------
// Mamba2 layer (B=4, L=2048, d_model=512, d_inner=1024, d_state=128, nheads=1)
// R3: cp.async-pipelined selective scan + register-staged double-buffered GEMM
// ---------------------------------------------------------------------------

typedef unsigned long long ull;

#define BATCH   4
#define SEQ     2048
#define TOK     (BATCH * SEQ)        // 8192
#define DMODEL  512
#define DINNER  1024
#define DSTATE  128
#define DPROJ   2305                 // 2*1024 + 2*128 + 1
#define CONVCH  1280                 // 1024 + 256

// scratch (static __device__ arrays; no cudaMalloc allowed)
__device__ float g_proj [(size_t)TOK * DPROJ];
__device__ float g_xconv[(size_t)TOK * CONVCH];
__device__ float g_dt   [TOK];
__device__ float g_dA   [TOK];
__device__ float g_yraw [(size_t)TOK * DINNER];
__device__ float g_ynorm[(size_t)TOK * DINNER];

// ---------------- packed f32x2 helpers ----------------
__device__ __forceinline__ ull pk(float lo, float hi) {
    ull r; asm("mov.b64 %0, {%1, %2};" : "=l"(r) : "f"(lo), "f"(hi)); return r;
}
__device__ __forceinline__ float2 unpk(ull v) {
    float2 r; asm("mov.b64 {%0, %1}, %2;" : "=f"(r.x), "=f"(r.y) : "l"(v)); return r;
}
__device__ __forceinline__ ull fma2(ull a, ull b, ull c) {
    ull d; asm("fma.rn.f32x2 %0, %1, %2, %3;" : "=l"(d) : "l"(a), "l"(b), "l"(c)); return d;
}
__device__ __forceinline__ ull mul2(ull a, ull b) {
    ull d; asm("mul.rn.f32x2 %0, %1, %2;" : "=l"(d) : "l"(a), "l"(b)); return d;
}

// ---------------- cp.async helpers ----------------
__device__ __forceinline__ void cp_async16(void* smem, const void* gmem) {
    uint32_t s = (uint32_t)__cvta_generic_to_shared(smem);
    asm volatile("cp.async.cg.shared.global [%0], [%1], 16;\n" :: "r"(s), "l"(gmem));
}
__device__ __forceinline__ void cp_async4(void* smem, const void* gmem) {
    uint32_t s = (uint32_t)__cvta_generic_to_shared(smem);
    asm volatile("cp.async.ca.shared.global [%0], [%1], 4;\n" :: "r"(s), "l"(gmem));
}
__device__ __forceinline__ void cp_commit() {
    asm volatile("cp.async.commit_group;\n" ::);
}
template <int N>
__device__ __forceinline__ void cp_wait() {
    asm volatile("cp.async.wait_group %0;\n" :: "n"(N));
}

// ---------------------------------------------------------------------------
// fp32 GEMM:  C[M,N] = A[M,K] * B[N,K]^T  (row-major, K-major rows)
// 128x128 tile, Ktile=16, double-buffered smem, register-staged pipeline.
// Requires M % 128 == 0, K % 16 == 0.
// ---------------------------------------------------------------------------
__global__ void __launch_bounds__(256, 2)
gemm_nt(const float* __restrict__ A, const float* __restrict__ B,
        float* __restrict__ C, int M, int N, int K)
{
    __shared__ __align__(16) float As[2][16][132];
    __shared__ __align__(16) float Bs[2][16][132];

    const int tid = threadIdx.x;
    const int tx  = tid & 15;          // 0..15 -> N
    const int ty  = tid >> 4;          // 0..15 -> M
    const int mb  = blockIdx.y * 128;
    const int nb  = blockIdx.x * 128;

    // staging regs for next tile: 2 float4 of A, 2 float4 of B
    float4 ra[2], rb[2];
    // load mapping: q = tid + r*256 in [0,512): m = q>>2 (0..127), kq = q&3
    const int m0  = (tid + 0 * 256) >> 2, kq0 = (tid + 0 * 256) & 3;
    const int m1  = (tid + 1 * 256) >> 2, kq1 = (tid + 1 * 256) & 3;

    auto ldg_tile = [&](int k0) {
        ra[0] = *(const float4*)(A + (size_t)(mb + m0) * K + k0 + kq0 * 4);
        ra[1] = *(const float4*)(A + (size_t)(mb + m1) * K + k0 + kq1 * 4);
        rb[0] = make_float4(0.f, 0.f, 0.f, 0.f);
        rb[1] = make_float4(0.f, 0.f, 0.f, 0.f);
        if (nb + m0 < N) rb[0] = *(const float4*)(B + (size_t)(nb + m0) * K + k0 + kq0 * 4);
        if (nb + m1 < N) rb[1] = *(const float4*)(B + (size_t)(nb + m1) * K + k0 + kq1 * 4);
    };
    auto sts_tile = [&](int buf) {
        As[buf][kq0 * 4 + 0][m0] = ra[0].x;  As[buf][kq0 * 4 + 1][m0] = ra[0].y;
        As[buf][kq0 * 4 + 2][m0] = ra[0].z;  As[buf][kq0 * 4 + 3][m0] = ra[0].w;
        As[buf][kq1 * 4 + 0][m1] = ra[1].x;  As[buf][kq1 * 4 + 1][m1] = ra[1].y;
        As[buf][kq1 * 4 + 2][m1] = ra[1].z;  As[buf][kq1 * 4 + 3][m1] = ra[1].w;
        Bs[buf][kq0 * 4 + 0][m0] = rb[0].x;  Bs[buf][kq0 * 4 + 1][m0] = rb[0].y;
        Bs[buf][kq0 * 4 + 2][m0] = rb[0].z;  Bs[buf][kq0 * 4 + 3][m0] = rb[0].w;
        Bs[buf][kq1 * 4 + 0][m1] = rb[1].x;  Bs[buf][kq1 * 4 + 1][m1] = rb[1].y;
        Bs[buf][kq1 * 4 + 2][m1] = rb[1].z;  Bs[buf][kq1 * 4 + 3][m1] = rb[1].w;
    };

    ull acc[8][4];
#pragma unroll
    for (int i = 0; i < 8; i++)
#pragma unroll
        for (int j = 0; j < 4; j++) acc[i][j] = 0ull;

    const int nkt = K >> 4;

    ldg_tile(0);
    sts_tile(0);
    __syncthreads();

    for (int kt = 0; kt < nkt; kt++) {
        if (kt + 1 < nkt) ldg_tile((kt + 1) << 4);

        const int buf = kt & 1;
#pragma unroll
        for (int k = 0; k < 16; k++) {
            const float4 a0 = *(const float4*)&As[buf][k][ty * 8];
            const float4 a1 = *(const float4*)&As[buf][k][ty * 8 + 4];
            const ulonglong2 b01 = *(const ulonglong2*)&Bs[buf][k][tx * 8];
            const ulonglong2 b23 = *(const ulonglong2*)&Bs[buf][k][tx * 8 + 4];
            ull bv[4] = { b01.x, b01.y, b23.x, b23.y };
            ull ad[8] = { pk(a0.x, a0.x), pk(a0.y, a0.y), pk(a0.z, a0.z), pk(a0.w, a0.w),
                          pk(a1.x, a1.x), pk(a1.y, a1.y), pk(a1.z, a1.z), pk(a1.w, a1.w) };
#pragma unroll
            for (int i = 0; i < 8; i++)
#pragma unroll
                for (int j = 0; j < 4; j++)
                    acc[i][j] = fma2(ad[i], bv[j], acc[i][j]);
        }

        if (kt + 1 < nkt) {
            sts_tile((kt + 1) & 1);
            __syncthreads();
        }
    }

#pragma unroll
    for (int i = 0; i < 8; i++) {
        const size_t row = (size_t)(mb + ty * 8 + i) * N;
#pragma unroll
        for (int j = 0; j < 4; j++) {
            const float2 v = unpk(acc[i][j]);
            const int gn = nb + tx * 8 + j * 2;
            if (gn     < N) C[row + gn]     = v.x;
            if (gn + 1 < N) C[row + gn + 1] = v.y;
        }
    }
}

// ---------------------------------------------------------------------------
// dt = softplus(proj[:,2304] + dt_bias); dA = exp(dt * (-exp(A_log)))
// ---------------------------------------------------------------------------
__global__ void dtprep(const float* __restrict__ proj,
                       const float* __restrict__ dt_bias,
                       const float* __restrict__ A_log,
                       float* __restrict__ gdt, float* __restrict__ gdA)
{
    const int t = blockIdx.x * blockDim.x + threadIdx.x;
    if (t >= TOK) return;
    const float raw = proj[(size_t)t * DPROJ + (DPROJ - 1)] + dt_bias[0];
    const float dt  = (raw > 20.f) ? raw : log1pf(expf(raw));
    const float A   = -expf(A_log[0]);
    gdt[t] = dt;
    gdA[t] = expf(dt * A);
}

// ---------------------------------------------------------------------------
// causal depthwise conv1d (width 4) + bias + silu over the 1280 xBC channels
// ---------------------------------------------------------------------------
__global__ void conv_silu(const float* __restrict__ proj,
                          const float* __restrict__ cw,   // (1280,1,4)
                          const float* __restrict__ cb,
                          float* __restrict__ xconv)
{
    const int id = blockIdx.x * 256 + threadIdx.x;
    if (id >= TOK * CONVCH) return;
    const int c   = id % CONVCH;
    const int tkn = id / CONVCH;
    const int l   = tkn & (SEQ - 1);

    const float4 w = ((const float4*)cw)[c];      // taps k=0..3
    const float* col = proj + (size_t)tkn * DPROJ + DINNER + c;

    float acc = cb[c];
    acc += col[0] * w.w;
    if (l >= 1) acc += *(col - (size_t)DPROJ)     * w.z;
    if (l >= 2) acc += *(col - (size_t)2 * DPROJ) * w.y;
    if (l >= 3) acc += *(col - (size_t)3 * DPROJ) * w.x;

    acc = acc / (1.f + expf(-acc));               // silu
    xconv[(size_t)tkn * CONVCH + c] = acc;
}

// ---------------------------------------------------------------------------
// Selective scan. Grid (32 p-tiles, 4 batches), 128 threads.
// Thread owns 2 p x 16 n. cp.async 3-step lookahead into 4 smem buffers.
// ---------------------------------------------------------------------------
__global__ void __launch_bounds__(128)
scan_kernel(const float* __restrict__ xconv,
            const float* __restrict__ dts,
            const float* __restrict__ dAs,
            const float* __restrict__ Dp,
            float* __restrict__ yraw)
{
    const int b      = blockIdx.y;
    const int pbase  = blockIdx.x * 32;
    const int tid    = threadIdx.x;
    const int nslice = tid & 7;       // 8 slices of 16 n
    const int pair   = tid >> 3;      // 0..15 -> p pair
    const int p0     = pbase + pair * 2;

    __shared__ __align__(16) float sB[4][DSTATE];
    __shared__ __align__(16) float sC[4][DSTATE];
    __shared__ __align__(16) float sX[4][32];
    __shared__ float sS[4][2];        // dt, dA

    ull st0[8], st1[8];
#pragma unroll
    for (int i = 0; i < 8; i++) { st0[i] = 0ull; st1[i] = 0ull; }

    const float dval = Dp[0];

    auto issue_load = [&](int t, int buf) {
        const float* base = xconv + (size_t)(b * SEQ + t) * CONVCH;
        if (tid < 32) {
            cp_async16(&sB[buf][tid * 4], base + DINNER + tid * 4);
        } else if (tid < 64) {
            const int j = tid - 32;
            cp_async16(&sC[buf][j * 4], base + DINNER + DSTATE + j * 4);
        } else if (tid < 72) {
            const int j = tid - 64;
            cp_async16(&sX[buf][j * 4], base + pbase + j * 4);
        } else if (tid == 72) {
            cp_async4(&sS[buf][0], dts + b * SEQ + t);
        } else if (tid == 73) {
            cp_async4(&sS[buf][1], dAs + b * SEQ + t);
        }
    };

    // prologue: 3 stages in flight
    issue_load(0, 0); cp_commit();
    issue_load(1, 1); cp_commit();
    issue_load(2, 2); cp_commit();

    for (int t = 0; t < SEQ; ++t) {
        cp_wait<2>();          // group for step t has landed
        __syncthreads();       // publish + everyone done with buffer (t-1)&3

        if (t + 3 < SEQ) issue_load(t + 3, (t + 3) & 3);
        cp_commit();           // uniform group count (possibly empty)

        const int buf = t & 3;
        const float dtv = sS[buf][0];
        const float dAv = sS[buf][1];
        const float x0  = sX[buf][pair * 2 + 0];
        const float x1  = sX[buf][pair * 2 + 1];
        const ull u0p = pk(dtv * x0, dtv * x0);
        const ull u1p = pk(dtv * x1, dtv * x1);
        const ull dAp = pk(dAv, dAv);

        const ulonglong2* Bp = (const ulonglong2*)&sB[buf][nslice * 16];
        const ulonglong2* Cp = (const ulonglong2*)&sC[buf][nslice * 16];

        ull acc0 = 0ull, acc1 = 0ull;
#pragma unroll
        for (int q = 0; q < 4; q++) {
            const ulonglong2 Bq = Bp[q];
            const ulonglong2 Cq = Cp[q];
            st0[2 * q]     = fma2(dAp, st0[2 * q],     mul2(u0p, Bq.x));
            st0[2 * q + 1] = fma2(dAp, st0[2 * q + 1], mul2(u0p, Bq.y));
            st1[2 * q]     = fma2(dAp, st1[2 * q],     mul2(u1p, Bq.x));
            st1[2 * q + 1] = fma2(dAp, st1[2 * q + 1], mul2(u1p, Bq.y));
            acc0 = fma2(st0[2 * q],     Cq.x, acc0);
            acc0 = fma2(st0[2 * q + 1], Cq.y, acc0);
            acc1 = fma2(st1[2 * q],     Cq.x, acc1);
            acc1 = fma2(st1[2 * q + 1], Cq.y, acc1);
        }
        const float2 a0 = unpk(acc0);
        const float2 a1 = unpk(acc1);
        float y0 = a0.x + a0.y;
        float y1 = a1.x + a1.y;
#pragma unroll
        for (int m = 1; m < 8; m <<= 1) {
            y0 += __shfl_xor_sync(0xffffffffu, y0, m);
            y1 += __shfl_xor_sync(0xffffffffu, y1, m);
        }
        if (nslice == 0) {
            float* o = yraw + (size_t)(b * SEQ + t) * DINNER + p0;
            o[0] = y0 + dval * x0;
            o[1] = y1 + dval * x1;
        }
    }
}

// ---------------------------------------------------------------------------
// y = yraw * silu(z); y = y * rsqrt(mean(y^2)+eps) * norm_w
// ---------------------------------------------------------------------------
__global__ void gate_norm(const float* __restrict__ yraw,
                          const float* __restrict__ proj,
                          const float* __restrict__ normw,
                          float* __restrict__ ynorm)
{
    const int t   = blockIdx.x;
    const int tid = threadIdx.x;

    float v[4];
    float ss = 0.f;
#pragma unroll
    for (int j = 0; j < 4; j++) {
        const int p = tid + j * 256;
        const float y = yraw[(size_t)t * DINNER + p];
        const float z = proj[(size_t)t * DPROJ + p];
        const float g = z / (1.f + expf(-z));
        const float val = y * g;
        v[j] = val;
        ss += val * val;
    }
#pragma unroll
    for (int m = 16; m; m >>= 1) ss += __shfl_xor_sync(0xffffffffu, ss, m);

    __shared__ float warpsum[8];
    __shared__ float inv_s;
    if ((tid & 31) == 0) warpsum[tid >> 5] = ss;
    __syncthreads();
    if (tid == 0) {
        float s = 0.f;
#pragma unroll
        for (int i = 0; i < 8; i++) s += warpsum[i];
        inv_s = rsqrtf(s * (1.f / DINNER) + 1e-5f);
    }
    __syncthreads();
    const float inv = inv_s;
#pragma unroll
    for (int j = 0; j < 4; j++) {
        const int p = tid + j * 256;
        ynorm[(size_t)t * DINNER + p] = v[j] * inv * normw[p];
    }
}

// ---------------------------------------------------------------------------
extern "C" void kernel_launch(void* const* d_in, const int* in_sizes, int n_in,
                              void* d_out, int out_size)
{
    const float* x       = (const float*)d_in[0];
    const float* rnn     = (const float*)d_in[1];
    const float* W_in    = (const float*)d_in[2];
    const float* conv_w  = (const float*)d_in[3];
    const float* conv_b  = (const float*)d_in[4];
    const float* dt_bias = (const float*)d_in[5];
    const float* A_log   = (const float*)d_in[6];
    const float* Dp      = (const float*)d_in[7];
    const float* norm_w  = (const float*)d_in[8];
    const float* W_out   = (const float*)d_in[9];
    float* out = (float*)d_out;

    float *proj, *xconv, *gdt, *gdA, *yraw, *ynorm;
    cudaGetSymbolAddress((void**)&proj,  g_proj);
    cudaGetSymbolAddress((void**)&xconv, g_xconv);
    cudaGetSymbolAddress((void**)&gdt,   g_dt);
    cudaGetSymbolAddress((void**)&gdA,   g_dA);
    cudaGetSymbolAddress((void**)&yraw,  g_yraw);
    cudaGetSymbolAddress((void**)&ynorm, g_ynorm);

    // 1) in-projection: proj[8192,2305] = x[8192,512] @ W_in[2305,512]^T
    gemm_nt<<<dim3((DPROJ + 127) / 128, TOK / 128), 256>>>(x, W_in, proj, TOK, DPROJ, DMODEL);

    // 2) dt / dA scalars
    dtprep<<<TOK / 256, 256>>>(proj, dt_bias, A_log, gdt, gdA);

    // 3) depthwise conv + silu on xBC channels
    conv_silu<<<(TOK * CONVCH + 255) / 256, 256>>>(proj, conv_w, conv_b, xconv);

    // 4) selective scan
    scan_kernel<<<dim3(32, BATCH), 128>>>(xconv, gdt, gdA, Dp, yraw);

    // 5) gate + RMSNorm
    gate_norm<<<TOK, 256>>>(yraw, proj, norm_w, ynorm);

    // 6) out-projection: out[8192,512] = ynorm[8192,1024] @ W_out[512,1024]^T
    gemm_nt<<<dim3(DMODEL / 128, TOK / 128), 256>>>(ynorm, W_out, out, TOK, DMODEL, DINNER);

    // 7) rnn_state passthrough (second tuple output)
    const int main_elems = TOK * DMODEL;
    if (out_size >= main_elems + BATCH * DMODEL) {
        cudaMemcpyAsync(out + main_elems, rnn, (size_t)BATCH * DMODEL * sizeof(float),
                        cudaMemcpyDeviceToDevice, 0);
    }
}

// round 10
// speedup vs baseline: 2.0459x; 1.3757x over previous
#include <cuda_runtime.h>
#include <cuda_bf16.h>
#include <cstdint>

// ---------------------------------------------------------------------------
// Mamba2 layer (B=4, L=2048, d_model=512, d_inner=1024, d_state=128, nheads=1)
// R10: mma.sync (base-target HMMA) bf16x3 GEMMs + fp32 dt GEMV +
//      cp.async-pipelined selective scan. No sm_103a-only instructions.
// ---------------------------------------------------------------------------

typedef unsigned long long ull;

#define BATCH   4
#define SEQ     2048
#define TOK     (BATCH * SEQ)        // 8192
#define DMODEL  512
#define DINNER  1024
#define DSTATE  128
#define NPROJ   2304                 // MMA-projected columns (z,xBC); dt col separate
#define PLD     2308                 // proj row stride (16B aligned)
#define CONVCH  1280                 // 1024 + 256

// ---------------- scratch (static __device__; no cudaMalloc allowed) -------
__device__ float g_proj [(size_t)TOK * PLD];
__device__ float g_xconv[(size_t)TOK * CONVCH];
__device__ float g_dt   [TOK];
__device__ float g_dA   [TOK];
__device__ float g_yraw [(size_t)TOK * DINNER];
__device__ float g_ynorm[(size_t)TOK * DINNER];
// bf16 hi/lo splits
__device__ __nv_bfloat16 g_xhi [(size_t)TOK * DMODEL];
__device__ __nv_bfloat16 g_xlo [(size_t)TOK * DMODEL];
__device__ __nv_bfloat16 g_wihi[(size_t)NPROJ * DMODEL];
__device__ __nv_bfloat16 g_wilo[(size_t)NPROJ * DMODEL];
__device__ __nv_bfloat16 g_yhi [(size_t)TOK * DINNER];
__device__ __nv_bfloat16 g_ylo [(size_t)TOK * DINNER];
__device__ __nv_bfloat16 g_wohi[(size_t)DMODEL * DINNER];
__device__ __nv_bfloat16 g_wolo[(size_t)DMODEL * DINNER];

// ---------------- packed f32x2 helpers ----------------
__device__ __forceinline__ ull pk(float lo, float hi) {
    ull r; asm("mov.b64 %0, {%1, %2};" : "=l"(r) : "f"(lo), "f"(hi)); return r;
}
__device__ __forceinline__ float2 unpk(ull v) {
    float2 r; asm("mov.b64 {%0, %1}, %2;" : "=f"(r.x), "=f"(r.y) : "l"(v)); return r;
}
__device__ __forceinline__ ull fma2(ull a, ull b, ull c) {
    ull d; asm("fma.rn.f32x2 %0, %1, %2, %3;" : "=l"(d) : "l"(a), "l"(b), "l"(c)); return d;
}
__device__ __forceinline__ ull mul2(ull a, ull b) {
    ull d; asm("mul.rn.f32x2 %0, %1, %2;" : "=l"(d) : "l"(a), "l"(b)); return d;
}

// ---------------- cp.async helpers ----------------
__device__ __forceinline__ void cp_async16(void* smem, const void* gmem) {
    uint32_t s = (uint32_t)__cvta_generic_to_shared(smem);
    asm volatile("cp.async.cg.shared.global [%0], [%1], 16;\n" :: "r"(s), "l"(gmem));
}
__device__ __forceinline__ void cp_async4(void* smem, const void* gmem) {
    uint32_t s = (uint32_t)__cvta_generic_to_shared(smem);
    asm volatile("cp.async.ca.shared.global [%0], [%1], 4;\n" :: "r"(s), "l"(gmem));
}
__device__ __forceinline__ void cp_commit() {
    asm volatile("cp.async.commit_group;\n" ::);
}
template <int N>
__device__ __forceinline__ void cp_wait() {
    asm volatile("cp.async.wait_group %0;\n" :: "n"(N));
}

// ---------------- mma.sync helpers (base target, sm_80+) ----------------
__device__ __forceinline__ void ldsm4(uint32_t& r0, uint32_t& r1, uint32_t& r2,
                                      uint32_t& r3, uint32_t addr) {
    asm volatile("ldmatrix.sync.aligned.m8n8.x4.shared.b16 {%0,%1,%2,%3}, [%4];"
                 : "=r"(r0), "=r"(r1), "=r"(r2), "=r"(r3) : "r"(addr));
}
__device__ __forceinline__ void mma16816(float* c, const uint32_t* a, const uint32_t* b) {
    asm volatile(
        "mma.sync.aligned.m16n8k16.row.col.f32.bf16.bf16.f32 "
        "{%0,%1,%2,%3}, {%4,%5,%6,%7}, {%8,%9}, {%0,%1,%2,%3};"
        : "+f"(c[0]), "+f"(c[1]), "+f"(c[2]), "+f"(c[3])
        : "r"(a[0]), "r"(a[1]), "r"(a[2]), "r"(a[3]), "r"(b[0]), "r"(b[1]));
}

// ---------------------------------------------------------------------------
// HMMA bf16x3 GEMM: C[M,N](fp32) = A[M,K]*B[N,K]^T, A/B pre-split hi/lo bf16.
// 128x128 CTA tile, BK=32, 256 thr (8 warps x 32m x 64n), cp.async dbl-buffer.
// Requires M%128==0, N%128==0, K%32==0.
// ---------------------------------------------------------------------------
#define BM 128
#define BN 128
#define BK 32
#define SK 40                         // smem row stride in bf16 (80B: LDSM conflict-free)
#define TILE_ELEMS (BM * SK)          // per matrix per buffer
#define GEMM_SMEM (2 * 4 * TILE_ELEMS * 2)   // 81920 bytes

__global__ void __launch_bounds__(256)
gemm_mma(const __nv_bfloat16* __restrict__ Ahi, const __nv_bfloat16* __restrict__ Alo,
         const __nv_bfloat16* __restrict__ Bhi, const __nv_bfloat16* __restrict__ Blo,
         float* __restrict__ C, int M, int N, int K, int ldc)
{
    extern __shared__ __align__(128) __nv_bfloat16 sm[];
    const int tid  = threadIdx.x;
    const int wid  = tid >> 5;
    const int lane = tid & 31;
    const int wm   = wid >> 1;        // 0..3: warp m (32 rows each)
    const int wn   = wid & 1;         // 0..1: warp n (64 cols each)
    const int mb   = blockIdx.y * BM;
    const int nb   = blockIdx.x * BN;
    const uint32_t sbase = (uint32_t)__cvta_generic_to_shared(sm);

    const __nv_bfloat16* gsrc[4] = {
        Ahi + (size_t)mb * K, Alo + (size_t)mb * K,
        Bhi + (size_t)nb * K, Blo + (size_t)nb * K };

    auto load_chunk = [&](int c, int buf) {
        const int k0 = c * BK;
#pragma unroll
        for (int mat = 0; mat < 4; mat++) {
            __nv_bfloat16* dst = sm + (buf * 4 + mat) * TILE_ELEMS;
            const __nv_bfloat16* src = gsrc[mat] + k0;
#pragma unroll
            for (int r = 0; r < 2; r++) {
                const int idx = tid + r * 256;       // 0..511
                const int row = idx >> 2;            // 0..127
                const int seg = idx & 3;             // 16B segment
                cp_async16(dst + row * SK + seg * 8, src + (size_t)row * K + seg * 8);
            }
        }
    };

    float acc[2][8][4];
#pragma unroll
    for (int i = 0; i < 2; i++)
#pragma unroll
        for (int j = 0; j < 8; j++)
#pragma unroll
            for (int q = 0; q < 4; q++) acc[i][j][q] = 0.f;

    const int NC = K / BK;

    load_chunk(0, 0); cp_commit();

    for (int c = 0; c < NC; ++c) {
        if (c + 1 < NC) { load_chunk(c + 1, (c + 1) & 1); cp_commit(); cp_wait<1>(); }
        else           { cp_wait<0>(); }
        __syncthreads();

        const int buf = c & 1;
        const uint32_t aHi = sbase + (buf * 4 + 0) * TILE_ELEMS * 2;
        const uint32_t aLo = sbase + (buf * 4 + 1) * TILE_ELEMS * 2;
        const uint32_t bHi = sbase + (buf * 4 + 2) * TILE_ELEMS * 2;
        const uint32_t bLo = sbase + (buf * 4 + 3) * TILE_ELEMS * 2;

        // A ldmatrix lane mapping: row=(l&15), koff=(l>>4)*8
        const int arow = (lane & 15);
        const int akof = (lane >> 4) << 3;
        // B ldmatrix lane mapping: nrel=((l>=16)?8:0)+(l&7), koff=((l>>3)&1)*8
        const int brow = ((lane >> 4) << 3) + (lane & 7);
        const int bkof = ((lane >> 3) & 1) << 3;

#pragma unroll
        for (int ks = 0; ks < 2; ks++) {
            uint32_t ah[2][4], al[2][4];
#pragma unroll
            for (int mf = 0; mf < 2; mf++) {
                const uint32_t off =
                    (uint32_t)((wm * 32 + mf * 16 + arow) * SK + ks * 16 + akof) * 2;
                ldsm4(ah[mf][0], ah[mf][1], ah[mf][2], ah[mf][3], aHi + off);
                ldsm4(al[mf][0], al[mf][1], al[mf][2], al[mf][3], aLo + off);
            }
#pragma unroll
            for (int nf2 = 0; nf2 < 4; nf2++) {
                const uint32_t off =
                    (uint32_t)((wn * 64 + nf2 * 16 + brow) * SK + ks * 16 + bkof) * 2;
                uint32_t bh[4], bl[4];
                ldsm4(bh[0], bh[1], bh[2], bh[3], bHi + off);
                ldsm4(bl[0], bl[1], bl[2], bl[3], bLo + off);
#pragma unroll
                for (int h = 0; h < 2; h++) {          // the two n8 frags in this pair
                    const int nf = nf2 * 2 + h;
#pragma unroll
                    for (int mf = 0; mf < 2; mf++) {
                        mma16816(acc[mf][nf], ah[mf], bh + h * 2);  // Ahi*Bhi
                        mma16816(acc[mf][nf], ah[mf], bl + h * 2);  // Ahi*Blo
                        mma16816(acc[mf][nf], al[mf], bh + h * 2);  // Alo*Bhi
                    }
                }
            }
        }
        __syncthreads();
    }

    // epilogue: c-frag m16n8 layout -> rows (lane>>2), (lane>>2)+8; cols (lane&3)*2
#pragma unroll
    for (int mf = 0; mf < 2; mf++) {
        const int r0 = mb + wm * 32 + mf * 16 + (lane >> 2);
#pragma unroll
        for (int nf = 0; nf < 8; nf++) {
            const int col = nb + wn * 64 + nf * 8 + (lane & 3) * 2;
            float2 v0 = make_float2(acc[mf][nf][0], acc[mf][nf][1]);
            float2 v1 = make_float2(acc[mf][nf][2], acc[mf][nf][3]);
            *(float2*)(C + (size_t)r0 * ldc + col)       = v0;
            *(float2*)(C + (size_t)(r0 + 8) * ldc + col) = v1;
        }
    }
}

// ---------------------------------------------------------------------------
// fp32 split -> (hi, lo) bf16
// ---------------------------------------------------------------------------
__global__ void split_bf16(const float* __restrict__ src,
                           __nv_bfloat16* __restrict__ hi,
                           __nv_bfloat16* __restrict__ lo, int n)
{
    const int i = blockIdx.x * 256 + threadIdx.x;
    if (i >= n) return;
    const float v = src[i];
    const __nv_bfloat16 h = __float2bfloat16(v);
    hi[i] = h;
    lo[i] = __float2bfloat16(v - __bfloat162float(h));
}

// ---------------------------------------------------------------------------
// dt column: exact fp32 GEMV raw[t] = x[t,:] . W_in[2304,:]; softplus; dA.
// One warp per token.
// ---------------------------------------------------------------------------
__global__ void dtprep(const float* __restrict__ x,
                       const float* __restrict__ Wrow,   // W_in + 2304*512
                       const float* __restrict__ dt_bias,
                       const float* __restrict__ A_log,
                       float* __restrict__ gdt, float* __restrict__ gdA)
{
    const int t    = blockIdx.x * 8 + (threadIdx.x >> 5);
    const int lane = threadIdx.x & 31;
    const float* xr = x + (size_t)t * DMODEL;
    float s = 0.f;
#pragma unroll
    for (int i = 0; i < 16; i++)
        s += xr[lane + 32 * i] * Wrow[lane + 32 * i];
#pragma unroll
    for (int m = 16; m; m >>= 1) s += __shfl_xor_sync(0xffffffffu, s, m);
    if (lane == 0) {
        const float raw = s + dt_bias[0];
        const float dt  = (raw > 20.f) ? raw : log1pf(expf(raw));
        gdt[t] = dt;
        gdA[t] = expf(dt * (-expf(A_log[0])));
    }
}

// ---------------------------------------------------------------------------
// causal depthwise conv1d (width 4) + bias + silu over the 1280 xBC channels
// ---------------------------------------------------------------------------
__global__ void conv_silu(const float* __restrict__ proj,
                          const float* __restrict__ cw,   // (1280,1,4)
                          const float* __restrict__ cb,
                          float* __restrict__ xconv)
{
    const int id = blockIdx.x * 256 + threadIdx.x;
    if (id >= TOK * CONVCH) return;
    const int c   = id % CONVCH;
    const int tkn = id / CONVCH;
    const int l   = tkn & (SEQ - 1);

    const float4 w = ((const float4*)cw)[c];      // taps k=0..3
    const float* col = proj + (size_t)tkn * PLD + DINNER + c;

    float acc = cb[c];
    acc += col[0] * w.w;
    if (l >= 1) acc += *(col - (size_t)PLD)     * w.z;
    if (l >= 2) acc += *(col - (size_t)2 * PLD) * w.y;
    if (l >= 3) acc += *(col - (size_t)3 * PLD) * w.x;

    acc = acc / (1.f + expf(-acc));               // silu
    xconv[(size_t)tkn * CONVCH + c] = acc;
}

// ---------------------------------------------------------------------------
// Selective scan. Grid (32 p-tiles, 4 batches), 128 threads.
// Thread owns 2 p x 16 n. cp.async 3-step lookahead into 4 smem buffers.
// ---------------------------------------------------------------------------
__global__ void __launch_bounds__(128)
scan_kernel(const float* __restrict__ xconv,
            const float* __restrict__ dts,
            const float* __restrict__ dAs,
            const float* __restrict__ Dp,
            float* __restrict__ yraw)
{
    const int b      = blockIdx.y;
    const int pbase  = blockIdx.x * 32;
    const int tid    = threadIdx.x;
    const int nslice = tid & 7;       // 8 slices of 16 n
    const int pair   = tid >> 3;      // 0..15 -> p pair
    const int p0     = pbase + pair * 2;

    __shared__ __align__(16) float sB[4][DSTATE];
    __shared__ __align__(16) float sC[4][DSTATE];
    __shared__ __align__(16) float sX[4][32];
    __shared__ float sS[4][2];        // dt, dA

    ull st0[8], st1[8];
#pragma unroll
    for (int i = 0; i < 8; i++) { st0[i] = 0ull; st1[i] = 0ull; }

    const float dval = Dp[0];

    auto issue_load = [&](int t, int buf) {
        const float* base = xconv + (size_t)(b * SEQ + t) * CONVCH;
        if (tid < 32) {
            cp_async16(&sB[buf][tid * 4], base + DINNER + tid * 4);
        } else if (tid < 64) {
            const int j = tid - 32;
            cp_async16(&sC[buf][j * 4], base + DINNER + DSTATE + j * 4);
        } else if (tid < 72) {
            const int j = tid - 64;
            cp_async16(&sX[buf][j * 4], base + pbase + j * 4);
        } else if (tid == 72) {
            cp_async4(&sS[buf][0], dts + b * SEQ + t);
        } else if (tid == 73) {
            cp_async4(&sS[buf][1], dAs + b * SEQ + t);
        }
    };

    issue_load(0, 0); cp_commit();
    issue_load(1, 1); cp_commit();
    issue_load(2, 2); cp_commit();

    for (int t = 0; t < SEQ; ++t) {
        cp_wait<2>();
        __syncthreads();

        if (t + 3 < SEQ) issue_load(t + 3, (t + 3) & 3);
        cp_commit();

        const int buf = t & 3;
        const float dtv = sS[buf][0];
        const float dAv = sS[buf][1];
        const float x0  = sX[buf][pair * 2 + 0];
        const float x1  = sX[buf][pair * 2 + 1];
        const ull u0p = pk(dtv * x0, dtv * x0);
        const ull u1p = pk(dtv * x1, dtv * x1);
        const ull dAp = pk(dAv, dAv);

        const ulonglong2* Bp = (const ulonglong2*)&sB[buf][nslice * 16];
        const ulonglong2* Cp = (const ulonglong2*)&sC[buf][nslice * 16];

        ull acc0 = 0ull, acc1 = 0ull;
#pragma unroll
        for (int q = 0; q < 4; q++) {
            const ulonglong2 Bq = Bp[q];
            const ulonglong2 Cq = Cp[q];
            st0[2 * q]     = fma2(dAp, st0[2 * q],     mul2(u0p, Bq.x));
            st0[2 * q + 1] = fma2(dAp, st0[2 * q + 1], mul2(u0p, Bq.y));
            st1[2 * q]     = fma2(dAp, st1[2 * q],     mul2(u1p, Bq.x));
            st1[2 * q + 1] = fma2(dAp, st1[2 * q + 1], mul2(u1p, Bq.y));
            acc0 = fma2(st0[2 * q],     Cq.x, acc0);
            acc0 = fma2(st0[2 * q + 1], Cq.y, acc0);
            acc1 = fma2(st1[2 * q],     Cq.x, acc1);
            acc1 = fma2(st1[2 * q + 1], Cq.y, acc1);
        }
        const float2 a0 = unpk(acc0);
        const float2 a1 = unpk(acc1);
        float y0 = a0.x + a0.y;
        float y1 = a1.x + a1.y;
#pragma unroll
        for (int m = 1; m < 8; m <<= 1) {
            y0 += __shfl_xor_sync(0xffffffffu, y0, m);
            y1 += __shfl_xor_sync(0xffffffffu, y1, m);
        }
        if (nslice == 0) {
            float* o = yraw + (size_t)(b * SEQ + t) * DINNER + p0;
            o[0] = y0 + dval * x0;
            o[1] = y1 + dval * x1;
        }
    }
}

// ---------------------------------------------------------------------------
// y = yraw * silu(z); y = y * rsqrt(mean(y^2)+eps) * norm_w
// ---------------------------------------------------------------------------
__global__ void gate_norm(const float* __restrict__ yraw,
                          const float* __restrict__ proj,
                          const float* __restrict__ normw,
                          float* __restrict__ ynorm)
{
    const int t   = blockIdx.x;
    const int tid = threadIdx.x;

    float v[4];
    float ss = 0.f;
#pragma unroll
    for (int j = 0; j < 4; j++) {
        const int p = tid + j * 256;
        const float y = yraw[(size_t)t * DINNER + p];
        const float z = proj[(size_t)t * PLD + p];
        const float g = z / (1.f + expf(-z));
        const float val = y * g;
        v[j] = val;
        ss += val * val;
    }
#pragma unroll
    for (int m = 16; m; m >>= 1) ss += __shfl_xor_sync(0xffffffffu, ss, m);

    __shared__ float warpsum[8];
    __shared__ float inv_s;
    if ((tid & 31) == 0) warpsum[tid >> 5] = ss;
    __syncthreads();
    if (tid == 0) {
        float s = 0.f;
#pragma unroll
        for (int i = 0; i < 8; i++) s += warpsum[i];
        inv_s = rsqrtf(s * (1.f / DINNER) + 1e-5f);
    }
    __syncthreads();
    const float inv = inv_s;
#pragma unroll
    for (int j = 0; j < 4; j++) {
        const int p = tid + j * 256;
        ynorm[(size_t)t * DINNER + p] = v[j] * inv * normw[p];
    }
}

// ---------------------------------------------------------------------------
extern "C" void kernel_launch(void* const* d_in, const int* in_sizes, int n_in,
                              void* d_out, int out_size)
{
    const float* x       = (const float*)d_in[0];
    const float* rnn     = (const float*)d_in[1];
    const float* W_in    = (const float*)d_in[2];
    const float* conv_w  = (const float*)d_in[3];
    const float* conv_b  = (const float*)d_in[4];
    const float* dt_bias = (const float*)d_in[5];
    const float* A_log   = (const float*)d_in[6];
    const float* Dp      = (const float*)d_in[7];
    const float* norm_w  = (const float*)d_in[8];
    const float* W_out   = (const float*)d_in[9];
    float* out = (float*)d_out;

    float *proj, *xconv, *gdt, *gdA, *yraw, *ynorm;
    __nv_bfloat16 *xhi, *xlo, *wihi, *wilo, *yhi, *ylo, *wohi, *wolo;
    cudaGetSymbolAddress((void**)&proj,  g_proj);
    cudaGetSymbolAddress((void**)&xconv, g_xconv);
    cudaGetSymbolAddress((void**)&gdt,   g_dt);
    cudaGetSymbolAddress((void**)&gdA,   g_dA);
    cudaGetSymbolAddress((void**)&yraw,  g_yraw);
    cudaGetSymbolAddress((void**)&ynorm, g_ynorm);
    cudaGetSymbolAddress((void**)&xhi,   g_xhi);
    cudaGetSymbolAddress((void**)&xlo,   g_xlo);
    cudaGetSymbolAddress((void**)&wihi,  g_wihi);
    cudaGetSymbolAddress((void**)&wilo,  g_wilo);
    cudaGetSymbolAddress((void**)&yhi,   g_yhi);
    cudaGetSymbolAddress((void**)&ylo,   g_ylo);
    cudaGetSymbolAddress((void**)&wohi,  g_wohi);
    cudaGetSymbolAddress((void**)&wolo,  g_wolo);

    cudaFuncSetAttribute(gemm_mma, cudaFuncAttributeMaxDynamicSharedMemorySize,
                         GEMM_SMEM);

    // 0) bf16 hi/lo splits for GEMM operands
    {
        const int nx = TOK * DMODEL;
        split_bf16<<<(nx + 255) / 256, 256>>>(x, xhi, xlo, nx);
        const int nw = NPROJ * DMODEL;
        split_bf16<<<(nw + 255) / 256, 256>>>(W_in, wihi, wilo, nw);
        const int no = DMODEL * DINNER;
        split_bf16<<<(no + 255) / 256, 256>>>(W_out, wohi, wolo, no);
    }

    // 1) in-projection (HMMA bf16x3): proj[:, 0:2304] = x @ W_in[0:2304]^T
    gemm_mma<<<dim3(NPROJ / 128, TOK / 128), 256, GEMM_SMEM>>>(
        xhi, xlo, wihi, wilo, proj, TOK, NPROJ, DMODEL, PLD);

    // 2) dt column in exact fp32 (GEMV) + softplus + dA
    dtprep<<<TOK / 8, 256>>>(x, W_in + (size_t)NPROJ * DMODEL, dt_bias, A_log, gdt, gdA);

    // 3) depthwise conv + silu on xBC channels
    conv_silu<<<(TOK * CONVCH + 255) / 256, 256>>>(proj, conv_w, conv_b, xconv);

    // 4) selective scan
    scan_kernel<<<dim3(32, BATCH), 128>>>(xconv, gdt, gdA, Dp, yraw);

    // 5) gate + RMSNorm
    gate_norm<<<TOK, 256>>>(yraw, proj, norm_w, ynorm);

    // 6) split ynorm, then out-projection (HMMA bf16x3)
    {
        const int ny = TOK * DINNER;
        split_bf16<<<(ny + 255) / 256, 256>>>(ynorm, yhi, ylo, ny);
    }
    gemm_mma<<<dim3(DMODEL / 128, TOK / 128), 256, GEMM_SMEM>>>(
        yhi, ylo, wohi, wolo, out, TOK, DMODEL, DINNER, DMODEL);

    // 7) rnn_state passthrough (second tuple output)
    const int main_elems = TOK * DMODEL;
    if (out_size >= main_elems + BATCH * DMODEL) {
        cudaMemcpyAsync(out + main_elems, rnn, (size_t)BATCH * DMODEL * sizeof(float),
                        cudaMemcpyDeviceToDevice, 0);
    }
}

// round 13
// speedup vs baseline: 4.6928x; 2.2938x over previous
#include <cuda_runtime.h>
#include <cuda_bf16.h>
#include <cstdint>

// ---------------------------------------------------------------------------
// Mamba2 layer (B=4, L=2048, d_model=512, d_inner=1024, d_state=128, nheads=1)
// R13 (= R11 resubmit after infra failure): chunked-SSD scan (all GEMMs) +
// mma.sync bf16x3 GEMMs + fp32 dt GEMV.
// ---------------------------------------------------------------------------

typedef unsigned long long ull;

#define BATCH   4
#define SEQ     2048
#define TOK     (BATCH * SEQ)        // 8192
#define DMODEL  512
#define DINNER  1024
#define DSTATE  128
#define NPROJ   2304
#define PLD     2308
#define CONVCH  1280
#define CH      128                  // chunk length
#define NCHUNK  16                   // chunks per batch
#define BJ      (BATCH * NCHUNK)     // 64 (b,chunk) pairs; token base = bj*128

// ---------------- scratch ----------------
__device__ float g_proj [(size_t)TOK * PLD];
__device__ float g_xconv[(size_t)TOK * CONVCH];
__device__ float g_dt   [TOK];
__device__ float g_la   [TOK];                       // log dA = dt*A
__device__ float g_yraw [(size_t)TOK * DINNER];
__device__ float g_ynorm[(size_t)TOK * DINNER];
__device__ __nv_bfloat16 g_xhi [(size_t)TOK * DMODEL];
__device__ __nv_bfloat16 g_xlo [(size_t)TOK * DMODEL];
__device__ __nv_bfloat16 g_wihi[(size_t)NPROJ * DMODEL];
__device__ __nv_bfloat16 g_wilo[(size_t)NPROJ * DMODEL];
__device__ __nv_bfloat16 g_yhi [(size_t)TOK * DINNER];
__device__ __nv_bfloat16 g_ylo [(size_t)TOK * DINNER];
__device__ __nv_bfloat16 g_wohi[(size_t)DMODEL * DINNER];
__device__ __nv_bfloat16 g_wolo[(size_t)DMODEL * DINNER];
// chunked-SSD buffers
__device__ __nv_bfloat16 g_acat_hi[(size_t)BJ * CH * 256];      // [M | P_i*C]
__device__ __nv_bfloat16 g_acat_lo[(size_t)BJ * CH * 256];
__device__ __nv_bfloat16 g_bcat_hi[(size_t)BJ * DINNER * 256];  // [U^T | h_in]
__device__ __nv_bfloat16 g_bcat_lo[(size_t)BJ * DINNER * 256];
__device__ __nv_bfloat16 g_u2t_hi [(size_t)BJ * DINNER * CH];   // (W1*u)^T
__device__ __nv_bfloat16 g_u2t_lo [(size_t)BJ * DINNER * CH];
__device__ __nv_bfloat16 g_bt2_hi [(size_t)BJ * DSTATE * CH];   // B^T
__device__ __nv_bfloat16 g_bt2_lo [(size_t)BJ * DSTATE * CH];
__device__ float g_sstate[(size_t)BJ * DINNER * DSTATE];        // chunk state incr
__device__ float g_w1[BJ * CH];                                 // exp(Llast-Ls)
__device__ float g_dj[BJ];                                      // exp(Llast)

// ---------------- cp.async helpers ----------------
__device__ __forceinline__ void cp_async16(void* smem, const void* gmem) {
    uint32_t s = (uint32_t)__cvta_generic_to_shared(smem);
    asm volatile("cp.async.cg.shared.global [%0], [%1], 16;\n" :: "r"(s), "l"(gmem));
}
__device__ __forceinline__ void cp_commit() {
    asm volatile("cp.async.commit_group;\n" ::);
}
template <int N>
__device__ __forceinline__ void cp_wait() {
    asm volatile("cp.async.wait_group %0;\n" :: "n"(N));
}

// ---------------- mma.sync helpers ----------------
__device__ __forceinline__ void ldsm4(uint32_t& r0, uint32_t& r1, uint32_t& r2,
                                      uint32_t& r3, uint32_t addr) {
    asm volatile("ldmatrix.sync.aligned.m8n8.x4.shared.b16 {%0,%1,%2,%3}, [%4];"
                 : "=r"(r0), "=r"(r1), "=r"(r2), "=r"(r3) : "r"(addr));
}
__device__ __forceinline__ void mma16816(float* c, const uint32_t* a, const uint32_t* b) {
    asm volatile(
        "mma.sync.aligned.m16n8k16.row.col.f32.bf16.bf16.f32 "
        "{%0,%1,%2,%3}, {%4,%5,%6,%7}, {%8,%9}, {%0,%1,%2,%3};"
        : "+f"(c[0]), "+f"(c[1]), "+f"(c[2]), "+f"(c[3])
        : "r"(a[0]), "r"(a[1]), "r"(a[2]), "r"(a[3]), "r"(b[0]), "r"(b[1]));
}

__device__ __forceinline__ __nv_bfloat162 split_hi2(float a, float b) {
    return __nv_bfloat162(__float2bfloat16(a), __float2bfloat16(b));
}
__device__ __forceinline__ __nv_bfloat162 split_lo2(float a, float b) {
    float ra = a - __bfloat162float(__float2bfloat16(a));
    float rb = b - __bfloat162float(__float2bfloat16(b));
    return __nv_bfloat162(__float2bfloat16(ra), __float2bfloat16(rb));
}

// ---------------------------------------------------------------------------
// HMMA bf16x3 GEMM (batched): C = A*B^T per batch z. K-major rows everywhere.
// 128x128 CTA tile, BK=32, 256 thr, cp.async double-buffered.
// ---------------------------------------------------------------------------
#define BM 128
#define BN 128
#define BK 32
#define SK 40
#define TILE_ELEMS (BM * SK)
#define GEMM_SMEM (2 * 4 * TILE_ELEMS * 2)   // 81920 bytes

__global__ void __launch_bounds__(256)
gemm_mma(const __nv_bfloat16* __restrict__ Ahi, const __nv_bfloat16* __restrict__ Alo,
         const __nv_bfloat16* __restrict__ Bhi, const __nv_bfloat16* __restrict__ Blo,
         float* __restrict__ C, int K, int ldc,
         size_t bsA, size_t bsB, size_t bsC)
{
    extern __shared__ __align__(128) __nv_bfloat16 sm[];
    const int tid  = threadIdx.x;
    const int wid  = tid >> 5;
    const int lane = tid & 31;
    const int wm   = wid >> 1;
    const int wn   = wid & 1;
    const int mb   = blockIdx.y * BM;
    const int nb   = blockIdx.x * BN;
    const size_t zA = (size_t)blockIdx.z * bsA;
    const size_t zB = (size_t)blockIdx.z * bsB;
    const size_t zC = (size_t)blockIdx.z * bsC;
    const uint32_t sbase = (uint32_t)__cvta_generic_to_shared(sm);

    const __nv_bfloat16* gsrc[4] = {
        Ahi + zA + (size_t)mb * K, Alo + zA + (size_t)mb * K,
        Bhi + zB + (size_t)nb * K, Blo + zB + (size_t)nb * K };

    auto load_chunk = [&](int c, int buf) {
        const int k0 = c * BK;
#pragma unroll
        for (int mat = 0; mat < 4; mat++) {
            __nv_bfloat16* dst = sm + (buf * 4 + mat) * TILE_ELEMS;
            const __nv_bfloat16* src = gsrc[mat] + k0;
#pragma unroll
            for (int r = 0; r < 2; r++) {
                const int idx = tid + r * 256;
                const int row = idx >> 2;
                const int seg = idx & 3;
                cp_async16(dst + row * SK + seg * 8, src + (size_t)row * K + seg * 8);
            }
        }
    };

    float acc[2][8][4];
#pragma unroll
    for (int i = 0; i < 2; i++)
#pragma unroll
        for (int j = 0; j < 8; j++)
#pragma unroll
            for (int q = 0; q < 4; q++) acc[i][j][q] = 0.f;

    const int NC = K / BK;
    load_chunk(0, 0); cp_commit();

    for (int c = 0; c < NC; ++c) {
        if (c + 1 < NC) { load_chunk(c + 1, (c + 1) & 1); cp_commit(); cp_wait<1>(); }
        else           { cp_wait<0>(); }
        __syncthreads();

        const int buf = c & 1;
        const uint32_t aHi = sbase + (buf * 4 + 0) * TILE_ELEMS * 2;
        const uint32_t aLo = sbase + (buf * 4 + 1) * TILE_ELEMS * 2;
        const uint32_t bHi = sbase + (buf * 4 + 2) * TILE_ELEMS * 2;
        const uint32_t bLo = sbase + (buf * 4 + 3) * TILE_ELEMS * 2;

        const int arow = (lane & 15);
        const int akof = (lane >> 4) << 3;
        const int brow = ((lane >> 4) << 3) + (lane & 7);
        const int bkof = ((lane >> 3) & 1) << 3;

#pragma unroll
        for (int ks = 0; ks < 2; ks++) {
            uint32_t ah[2][4], al[2][4];
#pragma unroll
            for (int mf = 0; mf < 2; mf++) {
                const uint32_t off =
                    (uint32_t)((wm * 32 + mf * 16 + arow) * SK + ks * 16 + akof) * 2;
                ldsm4(ah[mf][0], ah[mf][1], ah[mf][2], ah[mf][3], aHi + off);
                ldsm4(al[mf][0], al[mf][1], al[mf][2], al[mf][3], aLo + off);
            }
#pragma unroll
            for (int nf2 = 0; nf2 < 4; nf2++) {
                const uint32_t off =
                    (uint32_t)((wn * 64 + nf2 * 16 + brow) * SK + ks * 16 + bkof) * 2;
                uint32_t bh[4], bl[4];
                ldsm4(bh[0], bh[1], bh[2], bh[3], bHi + off);
                ldsm4(bl[0], bl[1], bl[2], bl[3], bLo + off);
#pragma unroll
                for (int h = 0; h < 2; h++) {
                    const int nf = nf2 * 2 + h;
#pragma unroll
                    for (int mf = 0; mf < 2; mf++) {
                        mma16816(acc[mf][nf], ah[mf], bh + h * 2);
                        mma16816(acc[mf][nf], ah[mf], bl + h * 2);
                        mma16816(acc[mf][nf], al[mf], bh + h * 2);
                    }
                }
            }
        }
        __syncthreads();
    }

#pragma unroll
    for (int mf = 0; mf < 2; mf++) {
        const int r0 = mb + wm * 32 + mf * 16 + (lane >> 2);
#pragma unroll
        for (int nf = 0; nf < 8; nf++) {
            const int col = nb + wn * 64 + nf * 8 + (lane & 3) * 2;
            *(float2*)(C + zC + (size_t)r0 * ldc + col) =
                make_float2(acc[mf][nf][0], acc[mf][nf][1]);
            *(float2*)(C + zC + (size_t)(r0 + 8) * ldc + col) =
                make_float2(acc[mf][nf][2], acc[mf][nf][3]);
        }
    }
}

// ---------------------------------------------------------------------------
// fp32 split -> (hi, lo) bf16
// ---------------------------------------------------------------------------
__global__ void split_bf16(const float* __restrict__ src,
                           __nv_bfloat16* __restrict__ hi,
                           __nv_bfloat16* __restrict__ lo, int n)
{
    const int i = blockIdx.x * 256 + threadIdx.x;
    if (i >= n) return;
    const float v = src[i];
    const __nv_bfloat16 h = __float2bfloat16(v);
    hi[i] = h;
    lo[i] = __float2bfloat16(v - __bfloat162float(h));
}

// ---------------------------------------------------------------------------
// dt GEMV (exact fp32) + softplus; la = dt*A (A = -exp(A_log))
// ---------------------------------------------------------------------------
__global__ void dtprep(const float* __restrict__ x,
                       const float* __restrict__ Wrow,
                       const float* __restrict__ dt_bias,
                       const float* __restrict__ A_log,
                       float* __restrict__ gdt, float* __restrict__ gla)
{
    const int t    = blockIdx.x * 8 + (threadIdx.x >> 5);
    const int lane = threadIdx.x & 31;
    const float* xr = x + (size_t)t * DMODEL;
    float s = 0.f;
#pragma unroll
    for (int i = 0; i < 16; i++)
        s += xr[lane + 32 * i] * Wrow[lane + 32 * i];
#pragma unroll
    for (int m = 16; m; m >>= 1) s += __shfl_xor_sync(0xffffffffu, s, m);
    if (lane == 0) {
        const float raw = s + dt_bias[0];
        const float dt  = (raw > 20.f) ? raw : log1pf(expf(raw));
        gdt[t] = dt;
        gla[t] = dt * (-expf(A_log[0]));
    }
}

// ---------------------------------------------------------------------------
// causal depthwise conv1d (width 4) + bias + silu
// ---------------------------------------------------------------------------
__global__ void conv_silu(const float* __restrict__ proj,
                          const float* __restrict__ cw,
                          const float* __restrict__ cb,
                          float* __restrict__ xconv)
{
    const int id = blockIdx.x * 256 + threadIdx.x;
    if (id >= TOK * CONVCH) return;
    const int c   = id % CONVCH;
    const int tkn = id / CONVCH;
    const int l   = tkn & (SEQ - 1);

    const float4 w = ((const float4*)cw)[c];
    const float* col = proj + (size_t)tkn * PLD + DINNER + c;

    float acc = cb[c];
    acc += col[0] * w.w;
    if (l >= 1) acc += *(col - (size_t)PLD)     * w.z;
    if (l >= 2) acc += *(col - (size_t)2 * PLD) * w.y;
    if (l >= 3) acc += *(col - (size_t)3 * PLD) * w.x;

    acc = acc / (1.f + expf(-acc));
    xconv[(size_t)tkn * CONVCH + c] = acc;
}

// ---------------------------------------------------------------------------
// S1 chunk_prep: per (b,j): L cumsum; G=C@B^T (fp32); M=G*exp(Li-Ls)*mask;
// Acat = [M | exp(Li)*C] hi/lo; W1[s]=exp(Llast-Ls); Dj=exp(Llast).
// 64 blocks x 256 threads; dyn smem = 2*128*132*4 + 1KB.
// ---------------------------------------------------------------------------
#define S1_SMEM (2 * 128 * 132 * 4 + 1024)
__global__ void __launch_bounds__(256)
chunk_prep(const float* __restrict__ xconv, const float* __restrict__ gla,
           __nv_bfloat16* __restrict__ acat_hi, __nv_bfloat16* __restrict__ acat_lo,
           float* __restrict__ W1, float* __restrict__ Dj)
{
    extern __shared__ float s1[];
    float* BT  = s1;                    // [n][s] stride 132
    float* Csm = s1 + 128 * 132;        // [i][n] stride 132
    float* sL  = Csm + 128 * 132;       // [128]
    float* sla = sL + 128;              // [128]
    const int bj  = blockIdx.x;
    const int tid = threadIdx.x;
    const int t0  = bj * CH;

    for (int idx = tid; idx < CH * DSTATE; idx += 256) {
        const int s = idx >> 7, n = idx & 127;
        const float* row = xconv + (size_t)(t0 + s) * CONVCH + DINNER;
        BT[n * 132 + s]  = row[n];
        Csm[s * 132 + n] = row[DSTATE + n];
    }
    if (tid < 128) sla[tid] = gla[t0 + tid];
    __syncthreads();
    if (tid == 0) {
        float run = 0.f;
        for (int i = 0; i < CH; i++) { run += sla[i]; sL[i] = run; }
    }
    __syncthreads();

    const int i     = tid & 127;
    const int sbase = (tid >> 7) * 64;
    float acc[64];
#pragma unroll
    for (int k = 0; k < 64; k++) acc[k] = 0.f;
    for (int n = 0; n < 128; n++) {
        const float c = Csm[i * 132 + n];
        const float4* bt = (const float4*)&BT[n * 132 + sbase];
#pragma unroll
        for (int k4 = 0; k4 < 16; k4++) {
            const float4 b4 = bt[k4];
            acc[k4 * 4 + 0] += c * b4.x;
            acc[k4 * 4 + 1] += c * b4.y;
            acc[k4 * 4 + 2] += c * b4.z;
            acc[k4 * 4 + 3] += c * b4.w;
        }
    }
    const float Li = sL[i];
#pragma unroll
    for (int k = 0; k < 64; k++) {
        const int s = sbase + k;
        const float m = (s <= i) ? acc[k] * expf(Li - sL[s]) : 0.f;
        const __nv_bfloat16 h = __float2bfloat16(m);
        const size_t o = ((size_t)bj * CH + i) * 256 + s;
        acat_hi[o] = h;
        acat_lo[o] = __float2bfloat16(m - __bfloat162float(h));
    }
    // Csc = exp(Li)*C into cols 128:256
    for (int idx = tid; idx < CH * DSTATE; idx += 256) {
        const int ii = idx >> 7, n = idx & 127;
        const float v = expf(sL[ii]) * Csm[ii * 132 + n];
        const __nv_bfloat16 h = __float2bfloat16(v);
        const size_t o = ((size_t)bj * CH + ii) * 256 + 128 + n;
        acat_hi[o] = h;
        acat_lo[o] = __float2bfloat16(v - __bfloat162float(h));
    }
    if (tid < 128) W1[bj * CH + tid] = expf(sL[127] - sL[tid]);
    if (tid == 0)  Dj[bj] = expf(sL[127]);
}

// ---------------------------------------------------------------------------
// uprep: U = dt*x, transposed into Bcat cols 0:128 (hi/lo) and W1-scaled into
// U2t (hi/lo). Grid (16 ptiles, 64 bj), 256 threads.
// ---------------------------------------------------------------------------
__global__ void __launch_bounds__(256)
uprep(const float* __restrict__ xconv, const float* __restrict__ gdt,
      const float* __restrict__ W1,
      __nv_bfloat16* __restrict__ bcat_hi, __nv_bfloat16* __restrict__ bcat_lo,
      __nv_bfloat16* __restrict__ u2t_hi,  __nv_bfloat16* __restrict__ u2t_lo)
{
    __shared__ float su[64 * 136];   // [p][s] stride 136
    __shared__ float sw[128];
    __shared__ float sdt[128];
    const int bj    = blockIdx.y;
    const int pbase = blockIdx.x * 64;
    const int tid   = threadIdx.x;
    const int t0    = bj * CH;

    if (tid < 128) { sw[tid] = W1[bj * CH + tid]; sdt[tid] = gdt[t0 + tid]; }
    __syncthreads();
    for (int idx = tid; idx < 64 * 128; idx += 256) {
        const int s = idx >> 6, p = idx & 63;
        su[p * 136 + s] = sdt[s] * xconv[(size_t)(t0 + s) * CONVCH + pbase + p];
    }
    __syncthreads();
    for (int idx = tid; idx < 64 * 64; idx += 256) {
        const int p = idx >> 6, s2 = idx & 63, s = s2 * 2;
        const float2 u = *(const float2*)&su[p * 136 + s];
        const size_t rB = ((size_t)bj * DINNER + pbase + p) * 256 + s;
        *(__nv_bfloat162*)&bcat_hi[rB] = split_hi2(u.x, u.y);
        *(__nv_bfloat162*)&bcat_lo[rB] = split_lo2(u.x, u.y);
        const float v0 = u.x * sw[s], v1 = u.y * sw[s + 1];
        const size_t rU = ((size_t)bj * DINNER + pbase + p) * 128 + s;
        *(__nv_bfloat162*)&u2t_hi[rU] = split_hi2(v0, v1);
        *(__nv_bfloat162*)&u2t_lo[rU] = split_lo2(v0, v1);
    }
}

// ---------------------------------------------------------------------------
// bprep: B chunk transposed -> Bt2[n][s] hi/lo. 64 blocks x 256 threads.
// ---------------------------------------------------------------------------
#define BPREP_SMEM (128 * 136 * 4)
__global__ void __launch_bounds__(256)
bprep(const float* __restrict__ xconv,
      __nv_bfloat16* __restrict__ bt2_hi, __nv_bfloat16* __restrict__ bt2_lo)
{
    extern __shared__ float sb[];   // [n][s] stride 136
    const int bj  = blockIdx.x;
    const int tid = threadIdx.x;
    const int t0  = bj * CH;
    for (int idx = tid; idx < 128 * 128; idx += 256) {
        const int s = idx >> 7, n = idx & 127;
        sb[n * 136 + s] = xconv[(size_t)(t0 + s) * CONVCH + DINNER + n];
    }
    __syncthreads();
    for (int idx = tid; idx < 128 * 64; idx += 256) {
        const int n = idx >> 6, s2 = idx & 63, s = s2 * 2;
        const float2 v = *(const float2*)&sb[n * 136 + s];
        const size_t o = ((size_t)bj * DSTATE + n) * 128 + s;
        *(__nv_bfloat162*)&bt2_hi[o] = split_hi2(v.x, v.y);
        *(__nv_bfloat162*)&bt2_lo[o] = split_lo2(v.x, v.y);
    }
}

// ---------------------------------------------------------------------------
// state_scan: h recurrence over 16 chunks; writes h_in (hi/lo) into Bcat cols
// 128:256. Thread = (b, p, n-pair). Grid 1024 x 256.
// ---------------------------------------------------------------------------
__global__ void __launch_bounds__(256)
state_scan(const float* __restrict__ S, const float* __restrict__ Dj,
           __nv_bfloat16* __restrict__ bcat_hi, __nv_bfloat16* __restrict__ bcat_lo)
{
    const int idx = blockIdx.x * 256 + threadIdx.x;     // 262144
    const int b   = idx >> 16;
    const int rem = idx & 65535;
    const int p   = rem >> 6;
    const int n   = (rem & 63) * 2;
    float2 h = make_float2(0.f, 0.f);
#pragma unroll
    for (int j = 0; j < NCHUNK; j++) {
        const int bj = b * NCHUNK + j;
        const size_t row = ((size_t)bj * DINNER + p) * 256 + 128 + n;
        *(__nv_bfloat162*)&bcat_hi[row] = split_hi2(h.x, h.y);
        *(__nv_bfloat162*)&bcat_lo[row] = split_lo2(h.x, h.y);
        const float d = Dj[bj];
        const float2 sv = *(const float2*)&S[((size_t)bj << 17) + p * 128 + n];
        h.x = d * h.x + sv.x;
        h.y = d * h.y + sv.y;
    }
}

// ---------------------------------------------------------------------------
// y = (yraw + D*x) * silu(z); RMSNorm
// ---------------------------------------------------------------------------
__global__ void gate_norm(const float* __restrict__ yraw,
                          const float* __restrict__ xconv,
                          const float* __restrict__ proj,
                          const float* __restrict__ normw,
                          const float* __restrict__ Dp,
                          float* __restrict__ ynorm)
{
    const int t   = blockIdx.x;
    const int tid = threadIdx.x;
    const float dval = Dp[0];

    float v[4];
    float ss = 0.f;
#pragma unroll
    for (int j = 0; j < 4; j++) {
        const int p = tid + j * 256;
        const float y = yraw[(size_t)t * DINNER + p]
                      + dval * xconv[(size_t)t * CONVCH + p];
        const float z = proj[(size_t)t * PLD + p];
        const float g = z / (1.f + expf(-z));
        const float val = y * g;
        v[j] = val;
        ss += val * val;
    }
#pragma unroll
    for (int m = 16; m; m >>= 1) ss += __shfl_xor_sync(0xffffffffu, ss, m);

    __shared__ float warpsum[8];
    __shared__ float inv_s;
    if ((tid & 31) == 0) warpsum[tid >> 5] = ss;
    __syncthreads();
    if (tid == 0) {
        float s = 0.f;
#pragma unroll
        for (int i = 0; i < 8; i++) s += warpsum[i];
        inv_s = rsqrtf(s * (1.f / DINNER) + 1e-5f);
    }
    __syncthreads();
    const float inv = inv_s;
#pragma unroll
    for (int j = 0; j < 4; j++) {
        const int p = tid + j * 256;
        ynorm[(size_t)t * DINNER + p] = v[j] * inv * normw[p];
    }
}

// ---------------------------------------------------------------------------
extern "C" void kernel_launch(void* const* d_in, const int* in_sizes, int n_in,
                              void* d_out, int out_size)
{
    const float* x       = (const float*)d_in[0];
    const float* rnn     = (const float*)d_in[1];
    const float* W_in    = (const float*)d_in[2];
    const float* conv_w  = (const float*)d_in[3];
    const float* conv_b  = (const float*)d_in[4];
    const float* dt_bias = (const float*)d_in[5];
    const float* A_log   = (const float*)d_in[6];
    const float* Dp      = (const float*)d_in[7];
    const float* norm_w  = (const float*)d_in[8];
    const float* W_out   = (const float*)d_in[9];
    float* out = (float*)d_out;

    float *proj, *xconv, *gdt, *gla, *yraw, *ynorm, *sstate, *w1, *dj;
    __nv_bfloat16 *xhi, *xlo, *wihi, *wilo, *yhi, *ylo, *wohi, *wolo;
    __nv_bfloat16 *acat_hi, *acat_lo, *bcat_hi, *bcat_lo;
    __nv_bfloat16 *u2t_hi, *u2t_lo, *bt2_hi, *bt2_lo;
    cudaGetSymbolAddress((void**)&proj,    g_proj);
    cudaGetSymbolAddress((void**)&xconv,   g_xconv);
    cudaGetSymbolAddress((void**)&gdt,     g_dt);
    cudaGetSymbolAddress((void**)&gla,     g_la);
    cudaGetSymbolAddress((void**)&yraw,    g_yraw);
    cudaGetSymbolAddress((void**)&ynorm,   g_ynorm);
    cudaGetSymbolAddress((void**)&xhi,     g_xhi);
    cudaGetSymbolAddress((void**)&xlo,     g_xlo);
    cudaGetSymbolAddress((void**)&wihi,    g_wihi);
    cudaGetSymbolAddress((void**)&wilo,    g_wilo);
    cudaGetSymbolAddress((void**)&yhi,     g_yhi);
    cudaGetSymbolAddress((void**)&ylo,     g_ylo);
    cudaGetSymbolAddress((void**)&wohi,    g_wohi);
    cudaGetSymbolAddress((void**)&wolo,    g_wolo);
    cudaGetSymbolAddress((void**)&acat_hi, g_acat_hi);
    cudaGetSymbolAddress((void**)&acat_lo, g_acat_lo);
    cudaGetSymbolAddress((void**)&bcat_hi, g_bcat_hi);
    cudaGetSymbolAddress((void**)&bcat_lo, g_bcat_lo);
    cudaGetSymbolAddress((void**)&u2t_hi,  g_u2t_hi);
    cudaGetSymbolAddress((void**)&u2t_lo,  g_u2t_lo);
    cudaGetSymbolAddress((void**)&bt2_hi,  g_bt2_hi);
    cudaGetSymbolAddress((void**)&bt2_lo,  g_bt2_lo);
    cudaGetSymbolAddress((void**)&sstate,  g_sstate);
    cudaGetSymbolAddress((void**)&w1,      g_w1);
    cudaGetSymbolAddress((void**)&dj,      g_dj);

    cudaFuncSetAttribute(gemm_mma, cudaFuncAttributeMaxDynamicSharedMemorySize,
                         GEMM_SMEM);
    cudaFuncSetAttribute(chunk_prep, cudaFuncAttributeMaxDynamicSharedMemorySize,
                         S1_SMEM);
    cudaFuncSetAttribute(bprep, cudaFuncAttributeMaxDynamicSharedMemorySize,
                         BPREP_SMEM);

    // 0) bf16 splits of GEMM operands
    split_bf16<<<(TOK * DMODEL + 255) / 256, 256>>>(x, xhi, xlo, TOK * DMODEL);
    split_bf16<<<(NPROJ * DMODEL + 255) / 256, 256>>>(W_in, wihi, wilo, NPROJ * DMODEL);
    split_bf16<<<(DMODEL * DINNER + 255) / 256, 256>>>(W_out, wohi, wolo, DMODEL * DINNER);

    // 1) in-projection
    gemm_mma<<<dim3(NPROJ / 128, TOK / 128, 1), 256, GEMM_SMEM>>>(
        xhi, xlo, wihi, wilo, proj, DMODEL, PLD, 0, 0, 0);

    // 2) dt (exact fp32) + la
    dtprep<<<TOK / 8, 256>>>(x, W_in + (size_t)NPROJ * DMODEL, dt_bias, A_log, gdt, gla);

    // 3) conv + silu
    conv_silu<<<(TOK * CONVCH + 255) / 256, 256>>>(proj, conv_w, conv_b, xconv);

    // 4) chunked-SSD scan
    chunk_prep<<<BJ, 256, S1_SMEM>>>(xconv, gla, acat_hi, acat_lo, w1, dj);
    uprep<<<dim3(16, BJ), 256>>>(xconv, gdt, w1, bcat_hi, bcat_lo, u2t_hi, u2t_lo);
    bprep<<<BJ, 256, BPREP_SMEM>>>(xconv, bt2_hi, bt2_lo);
    // S_state[bj][p,n] = sum_s U2t[p,s] * Bt2[n,s]
    gemm_mma<<<dim3(1, DINNER / 128, BJ), 256, GEMM_SMEM>>>(
        u2t_hi, u2t_lo, bt2_hi, bt2_lo, sstate, 128, DSTATE,
        (size_t)DINNER * 128, (size_t)DSTATE * 128, (size_t)DINNER * DSTATE);
    state_scan<<<1024, 256>>>(sstate, dj, bcat_hi, bcat_lo);
    // yraw[bj][i,p] = Acat[i,:] . Bcat[p,:]  (K = 256)
    gemm_mma<<<dim3(DINNER / 128, 1, BJ), 256, GEMM_SMEM>>>(
        acat_hi, acat_lo, bcat_hi, bcat_lo, yraw, 256, DINNER,
        (size_t)CH * 256, (size_t)DINNER * 256, (size_t)CH * DINNER);

    // 5) gate + RMSNorm (D*x folded in)
    gate_norm<<<TOK, 256>>>(yraw, xconv, proj, norm_w, Dp, ynorm);

    // 6) out-projection
    split_bf16<<<(TOK * DINNER + 255) / 256, 256>>>(ynorm, yhi, ylo, TOK * DINNER);
    gemm_mma<<<dim3(DMODEL / 128, TOK / 128, 1), 256, GEMM_SMEM>>>(
        yhi, ylo, wohi, wolo, out, DINNER, DMODEL, 0, 0, 0);

    // 7) rnn_state passthrough
    const int main_elems = TOK * DMODEL;
    if (out_size >= main_elems + BATCH * DMODEL) {
        cudaMemcpyAsync(out + main_elems, rnn, (size_t)BATCH * DMODEL * sizeof(float),
                        cudaMemcpyDeviceToDevice, 0);
    }
}

// round 14
// speedup vs baseline: 5.1402x; 1.0953x over previous
#include <cuda_runtime.h>
#include <cuda_bf16.h>
#include <cstdint>

// ---------------------------------------------------------------------------
// Mamba2 layer (B=4, L=2048, d_model=512, d_inner=1024, d_state=128, nheads=1)
// R14: R13 + pipelined B-fragment ldmatrix in gemm_mma + gate_norm direct
// hi/lo output + sliding-window conv.
// ---------------------------------------------------------------------------

typedef unsigned long long ull;

#define BATCH   4
#define SEQ     2048
#define TOK     (BATCH * SEQ)        // 8192
#define DMODEL  512
#define DINNER  1024
#define DSTATE  128
#define NPROJ   2304
#define PLD     2308
#define CONVCH  1280
#define CH      128                  // chunk length
#define NCHUNK  16                   // chunks per batch
#define BJ      (BATCH * NCHUNK)     // 64 (b,chunk) pairs; token base = bj*128

// ---------------- scratch ----------------
__device__ float g_proj [(size_t)TOK * PLD];
__device__ float g_xconv[(size_t)TOK * CONVCH];
__device__ float g_dt   [TOK];
__device__ float g_la   [TOK];
__device__ float g_yraw [(size_t)TOK * DINNER];
__device__ __nv_bfloat16 g_xhi [(size_t)TOK * DMODEL];
__device__ __nv_bfloat16 g_xlo [(size_t)TOK * DMODEL];
__device__ __nv_bfloat16 g_wihi[(size_t)NPROJ * DMODEL];
__device__ __nv_bfloat16 g_wilo[(size_t)NPROJ * DMODEL];
__device__ __nv_bfloat16 g_yhi [(size_t)TOK * DINNER];
__device__ __nv_bfloat16 g_ylo [(size_t)TOK * DINNER];
__device__ __nv_bfloat16 g_wohi[(size_t)DMODEL * DINNER];
__device__ __nv_bfloat16 g_wolo[(size_t)DMODEL * DINNER];
// chunked-SSD buffers
__device__ __nv_bfloat16 g_acat_hi[(size_t)BJ * CH * 256];      // [M | P_i*C]
__device__ __nv_bfloat16 g_acat_lo[(size_t)BJ * CH * 256];
__device__ __nv_bfloat16 g_bcat_hi[(size_t)BJ * DINNER * 256];  // [U^T | h_in]
__device__ __nv_bfloat16 g_bcat_lo[(size_t)BJ * DINNER * 256];
__device__ __nv_bfloat16 g_u2t_hi [(size_t)BJ * DINNER * CH];   // (W1*u)^T
__device__ __nv_bfloat16 g_u2t_lo [(size_t)BJ * DINNER * CH];
__device__ __nv_bfloat16 g_bt2_hi [(size_t)BJ * DSTATE * CH];   // B^T
__device__ __nv_bfloat16 g_bt2_lo [(size_t)BJ * DSTATE * CH];
__device__ float g_sstate[(size_t)BJ * DINNER * DSTATE];        // chunk state incr
__device__ float g_w1[BJ * CH];                                 // exp(Llast-Ls)
__device__ float g_dj[BJ];                                      // exp(Llast)

// ---------------- cp.async helpers ----------------
__device__ __forceinline__ void cp_async16(void* smem, const void* gmem) {
    uint32_t s = (uint32_t)__cvta_generic_to_shared(smem);
    asm volatile("cp.async.cg.shared.global [%0], [%1], 16;\n" :: "r"(s), "l"(gmem));
}
__device__ __forceinline__ void cp_commit() {
    asm volatile("cp.async.commit_group;\n" ::);
}
template <int N>
__device__ __forceinline__ void cp_wait() {
    asm volatile("cp.async.wait_group %0;\n" :: "n"(N));
}

// ---------------- mma.sync helpers ----------------
__device__ __forceinline__ void ldsm4(uint32_t& r0, uint32_t& r1, uint32_t& r2,
                                      uint32_t& r3, uint32_t addr) {
    asm volatile("ldmatrix.sync.aligned.m8n8.x4.shared.b16 {%0,%1,%2,%3}, [%4];"
                 : "=r"(r0), "=r"(r1), "=r"(r2), "=r"(r3) : "r"(addr));
}
__device__ __forceinline__ void mma16816(float* c, const uint32_t* a, const uint32_t* b) {
    asm volatile(
        "mma.sync.aligned.m16n8k16.row.col.f32.bf16.bf16.f32 "
        "{%0,%1,%2,%3}, {%4,%5,%6,%7}, {%8,%9}, {%0,%1,%2,%3};"
        : "+f"(c[0]), "+f"(c[1]), "+f"(c[2]), "+f"(c[3])
        : "r"(a[0]), "r"(a[1]), "r"(a[2]), "r"(a[3]), "r"(b[0]), "r"(b[1]));
}

__device__ __forceinline__ __nv_bfloat162 split_hi2(float a, float b) {
    return __nv_bfloat162(__float2bfloat16(a), __float2bfloat16(b));
}
__device__ __forceinline__ __nv_bfloat162 split_lo2(float a, float b) {
    float ra = a - __bfloat162float(__float2bfloat16(a));
    float rb = b - __bfloat162float(__float2bfloat16(b));
    return __nv_bfloat162(__float2bfloat16(ra), __float2bfloat16(rb));
}

// ---------------------------------------------------------------------------
// HMMA bf16x3 GEMM (batched): C = A*B^T per batch z. K-major rows everywhere.
// 128x128 CTA tile, BK=32, 256 thr, cp.async double-buffered, B-fragment
// ldmatrix software pipeline (hides LDS latency under MMAs).
// ---------------------------------------------------------------------------
#define BM 128
#define BN 128
#define BK 32
#define SK 40
#define TILE_ELEMS (BM * SK)
#define GEMM_SMEM (2 * 4 * TILE_ELEMS * 2)   // 81920 bytes

__global__ void __launch_bounds__(256)
gemm_mma(const __nv_bfloat16* __restrict__ Ahi, const __nv_bfloat16* __restrict__ Alo,
         const __nv_bfloat16* __restrict__ Bhi, const __nv_bfloat16* __restrict__ Blo,
         float* __restrict__ C, int K, int ldc,
         size_t bsA, size_t bsB, size_t bsC)
{
    extern __shared__ __align__(128) __nv_bfloat16 sm[];
    const int tid  = threadIdx.x;
    const int wid  = tid >> 5;
    const int lane = tid & 31;
    const int wm   = wid >> 1;
    const int wn   = wid & 1;
    const int mb   = blockIdx.y * BM;
    const int nb   = blockIdx.x * BN;
    const size_t zA = (size_t)blockIdx.z * bsA;
    const size_t zB = (size_t)blockIdx.z * bsB;
    const size_t zC = (size_t)blockIdx.z * bsC;
    const uint32_t sbase = (uint32_t)__cvta_generic_to_shared(sm);

    const __nv_bfloat16* gsrc[4] = {
        Ahi + zA + (size_t)mb * K, Alo + zA + (size_t)mb * K,
        Bhi + zB + (size_t)nb * K, Blo + zB + (size_t)nb * K };

    auto load_chunk = [&](int c, int buf) {
        const int k0 = c * BK;
#pragma unroll
        for (int mat = 0; mat < 4; mat++) {
            __nv_bfloat16* dst = sm + (buf * 4 + mat) * TILE_ELEMS;
            const __nv_bfloat16* src = gsrc[mat] + k0;
#pragma unroll
            for (int r = 0; r < 2; r++) {
                const int idx = tid + r * 256;
                const int row = idx >> 2;
                const int seg = idx & 3;
                cp_async16(dst + row * SK + seg * 8, src + (size_t)row * K + seg * 8);
            }
        }
    };

    float acc[2][8][4];
#pragma unroll
    for (int i = 0; i < 2; i++)
#pragma unroll
        for (int j = 0; j < 8; j++)
#pragma unroll
            for (int q = 0; q < 4; q++) acc[i][j][q] = 0.f;

    const int NC = K / BK;
    load_chunk(0, 0); cp_commit();

    const int arow = (lane & 15);
    const int akof = (lane >> 4) << 3;
    const int brow = ((lane >> 4) << 3) + (lane & 7);
    const int bkof = ((lane >> 3) & 1) << 3;

    for (int c = 0; c < NC; ++c) {
        if (c + 1 < NC) { load_chunk(c + 1, (c + 1) & 1); cp_commit(); cp_wait<1>(); }
        else           { cp_wait<0>(); }
        __syncthreads();

        const int buf = c & 1;
        const uint32_t aHi = sbase + (buf * 4 + 0) * TILE_ELEMS * 2;
        const uint32_t aLo = sbase + (buf * 4 + 1) * TILE_ELEMS * 2;
        const uint32_t bHi = sbase + (buf * 4 + 2) * TILE_ELEMS * 2;
        const uint32_t bLo = sbase + (buf * 4 + 3) * TILE_ELEMS * 2;

#pragma unroll
        for (int ks = 0; ks < 2; ks++) {
            uint32_t ah[2][4], al[2][4];
#pragma unroll
            for (int mf = 0; mf < 2; mf++) {
                const uint32_t off =
                    (uint32_t)((wm * 32 + mf * 16 + arow) * SK + ks * 16 + akof) * 2;
                ldsm4(ah[mf][0], ah[mf][1], ah[mf][2], ah[mf][3], aHi + off);
                ldsm4(al[mf][0], al[mf][1], al[mf][2], al[mf][3], aLo + off);
            }
            // double-buffered B fragments: prefetch nf2+1 while computing nf2
            uint32_t bh[2][4], bl[2][4];
            {
                const uint32_t off0 =
                    (uint32_t)((wn * 64 + brow) * SK + ks * 16 + bkof) * 2;
                ldsm4(bh[0][0], bh[0][1], bh[0][2], bh[0][3], bHi + off0);
                ldsm4(bl[0][0], bl[0][1], bl[0][2], bl[0][3], bLo + off0);
            }
#pragma unroll
            for (int nf2 = 0; nf2 < 4; nf2++) {
                const int cur = nf2 & 1;
                const int nxt = cur ^ 1;
                if (nf2 < 3) {
                    const uint32_t offn =
                        (uint32_t)((wn * 64 + (nf2 + 1) * 16 + brow) * SK
                                   + ks * 16 + bkof) * 2;
                    ldsm4(bh[nxt][0], bh[nxt][1], bh[nxt][2], bh[nxt][3], bHi + offn);
                    ldsm4(bl[nxt][0], bl[nxt][1], bl[nxt][2], bl[nxt][3], bLo + offn);
                }
#pragma unroll
                for (int h = 0; h < 2; h++) {
                    const int nf = nf2 * 2 + h;
#pragma unroll
                    for (int mf = 0; mf < 2; mf++) {
                        mma16816(acc[mf][nf], ah[mf], &bh[cur][h * 2]);
                        mma16816(acc[mf][nf], ah[mf], &bl[cur][h * 2]);
                        mma16816(acc[mf][nf], al[mf], &bh[cur][h * 2]);
                    }
                }
            }
        }
        __syncthreads();
    }

#pragma unroll
    for (int mf = 0; mf < 2; mf++) {
        const int r0 = mb + wm * 32 + mf * 16 + (lane >> 2);
#pragma unroll
        for (int nf = 0; nf < 8; nf++) {
            const int col = nb + wn * 64 + nf * 8 + (lane & 3) * 2;
            *(float2*)(C + zC + (size_t)r0 * ldc + col) =
                make_float2(acc[mf][nf][0], acc[mf][nf][1]);
            *(float2*)(C + zC + (size_t)(r0 + 8) * ldc + col) =
                make_float2(acc[mf][nf][2], acc[mf][nf][3]);
        }
    }
}

// ---------------------------------------------------------------------------
// fp32 split -> (hi, lo) bf16
// ---------------------------------------------------------------------------
__global__ void split_bf16(const float* __restrict__ src,
                           __nv_bfloat16* __restrict__ hi,
                           __nv_bfloat16* __restrict__ lo, int n)
{
    const int i = blockIdx.x * 256 + threadIdx.x;
    if (i >= n) return;
    const float v = src[i];
    const __nv_bfloat16 h = __float2bfloat16(v);
    hi[i] = h;
    lo[i] = __float2bfloat16(v - __bfloat162float(h));
}

// ---------------------------------------------------------------------------
// dt GEMV (exact fp32) + softplus; la = dt*A (A = -exp(A_log))
// ---------------------------------------------------------------------------
__global__ void dtprep(const float* __restrict__ x,
                       const float* __restrict__ Wrow,
                       const float* __restrict__ dt_bias,
                       const float* __restrict__ A_log,
                       float* __restrict__ gdt, float* __restrict__ gla)
{
    const int t    = blockIdx.x * 8 + (threadIdx.x >> 5);
    const int lane = threadIdx.x & 31;
    const float* xr = x + (size_t)t * DMODEL;
    float s = 0.f;
#pragma unroll
    for (int i = 0; i < 16; i++)
        s += xr[lane + 32 * i] * Wrow[lane + 32 * i];
#pragma unroll
    for (int m = 16; m; m >>= 1) s += __shfl_xor_sync(0xffffffffu, s, m);
    if (lane == 0) {
        const float raw = s + dt_bias[0];
        const float dt  = (raw > 20.f) ? raw : log1pf(expf(raw));
        gdt[t] = dt;
        gla[t] = dt * (-expf(A_log[0]));
    }
}

// ---------------------------------------------------------------------------
// causal depthwise conv1d (width 4) + bias + silu, sliding window:
// one thread produces 4 consecutive l for one channel (7 loads / 4 outputs).
// ---------------------------------------------------------------------------
__global__ void conv_silu(const float* __restrict__ proj,
                          const float* __restrict__ cw,
                          const float* __restrict__ cb,
                          float* __restrict__ xconv)
{
    const int id = blockIdx.x * 256 + threadIdx.x;
    if (id >= (TOK / 4) * CONVCH) return;
    const int c    = id % CONVCH;
    const int q    = id / CONVCH;
    const int tkn0 = q * 4;                 // 4 tokens, same batch (SEQ%4==0)
    const int l0   = tkn0 & (SEQ - 1);

    const float4 w = ((const float4*)cw)[c];    // taps k=0..3 (x..w)
    const float  b = cb[c];
    const size_t col = (size_t)tkn0 * PLD + DINNER + c;

    float v[7];
#pragma unroll
    for (int j = 0; j < 7; j++) {
        const int dl = j - 3;                   // -3..3
        v[j] = (l0 + dl >= 0) ? proj[col + (ptrdiff_t)dl * PLD] : 0.f;
    }
#pragma unroll
    for (int j = 0; j < 4; j++) {
        float acc = b + w.x * v[j] + w.y * v[j + 1] + w.z * v[j + 2] + w.w * v[j + 3];
        acc = acc / (1.f + expf(-acc));
        xconv[(size_t)(tkn0 + j) * CONVCH + c] = acc;
    }
}

// ---------------------------------------------------------------------------
// S1 chunk_prep: per (b,j): L cumsum; G=C@B^T (fp32); M=G*exp(Li-Ls)*mask;
// Acat = [M | exp(Li)*C] hi/lo; W1[s]=exp(Llast-Ls); Dj=exp(Llast).
// ---------------------------------------------------------------------------
#define S1_SMEM (2 * 128 * 132 * 4 + 1024)
__global__ void __launch_bounds__(256)
chunk_prep(const float* __restrict__ xconv, const float* __restrict__ gla,
           __nv_bfloat16* __restrict__ acat_hi, __nv_bfloat16* __restrict__ acat_lo,
           float* __restrict__ W1, float* __restrict__ Dj)
{
    extern __shared__ float s1[];
    float* BT  = s1;                    // [n][s] stride 132
    float* Csm = s1 + 128 * 132;        // [i][n] stride 132
    float* sL  = Csm + 128 * 132;       // [128]
    float* sla = sL + 128;              // [128]
    const int bj  = blockIdx.x;
    const int tid = threadIdx.x;
    const int t0  = bj * CH;

    for (int idx = tid; idx < CH * DSTATE; idx += 256) {
        const int s = idx >> 7, n = idx & 127;
        const float* row = xconv + (size_t)(t0 + s) * CONVCH + DINNER;
        BT[n * 132 + s]  = row[n];
        Csm[s * 132 + n] = row[DSTATE + n];
    }
    if (tid < 128) sla[tid] = gla[t0 + tid];
    __syncthreads();
    if (tid == 0) {
        float run = 0.f;
        for (int i = 0; i < CH; i++) { run += sla[i]; sL[i] = run; }
    }
    __syncthreads();

    const int i     = tid & 127;
    const int sbase = (tid >> 7) * 64;
    float acc[64];
#pragma unroll
    for (int k = 0; k < 64; k++) acc[k] = 0.f;
    for (int n = 0; n < 128; n++) {
        const float c = Csm[i * 132 + n];
        const float4* bt = (const float4*)&BT[n * 132 + sbase];
#pragma unroll
        for (int k4 = 0; k4 < 16; k4++) {
            const float4 b4 = bt[k4];
            acc[k4 * 4 + 0] += c * b4.x;
            acc[k4 * 4 + 1] += c * b4.y;
            acc[k4 * 4 + 2] += c * b4.z;
            acc[k4 * 4 + 3] += c * b4.w;
        }
    }
    const float Li = sL[i];
#pragma unroll
    for (int k = 0; k < 64; k++) {
        const int s = sbase + k;
        const float m = (s <= i) ? acc[k] * expf(Li - sL[s]) : 0.f;
        const __nv_bfloat16 h = __float2bfloat16(m);
        const size_t o = ((size_t)bj * CH + i) * 256 + s;
        acat_hi[o] = h;
        acat_lo[o] = __float2bfloat16(m - __bfloat162float(h));
    }
    for (int idx = tid; idx < CH * DSTATE; idx += 256) {
        const int ii = idx >> 7, n = idx & 127;
        const float v = expf(sL[ii]) * Csm[ii * 132 + n];
        const __nv_bfloat16 h = __float2bfloat16(v);
        const size_t o = ((size_t)bj * CH + ii) * 256 + 128 + n;
        acat_hi[o] = h;
        acat_lo[o] = __float2bfloat16(v - __bfloat162float(h));
    }
    if (tid < 128) W1[bj * CH + tid] = expf(sL[127] - sL[tid]);
    if (tid == 0)  Dj[bj] = expf(sL[127]);
}

// ---------------------------------------------------------------------------
// uprep: U = dt*x transposed into Bcat cols 0:128 and W1-scaled into U2t.
// ---------------------------------------------------------------------------
__global__ void __launch_bounds__(256)
uprep(const float* __restrict__ xconv, const float* __restrict__ gdt,
      const float* __restrict__ W1,
      __nv_bfloat16* __restrict__ bcat_hi, __nv_bfloat16* __restrict__ bcat_lo,
      __nv_bfloat16* __restrict__ u2t_hi,  __nv_bfloat16* __restrict__ u2t_lo)
{
    __shared__ float su[64 * 136];
    __shared__ float sw[128];
    __shared__ float sdt[128];
    const int bj    = blockIdx.y;
    const int pbase = blockIdx.x * 64;
    const int tid   = threadIdx.x;
    const int t0    = bj * CH;

    if (tid < 128) { sw[tid] = W1[bj * CH + tid]; sdt[tid] = gdt[t0 + tid]; }
    __syncthreads();
    for (int idx = tid; idx < 64 * 128; idx += 256) {
        const int s = idx >> 6, p = idx & 63;
        su[p * 136 + s] = sdt[s] * xconv[(size_t)(t0 + s) * CONVCH + pbase + p];
    }
    __syncthreads();
    for (int idx = tid; idx < 64 * 64; idx += 256) {
        const int p = idx >> 6, s2 = idx & 63, s = s2 * 2;
        const float2 u = *(const float2*)&su[p * 136 + s];
        const size_t rB = ((size_t)bj * DINNER + pbase + p) * 256 + s;
        *(__nv_bfloat162*)&bcat_hi[rB] = split_hi2(u.x, u.y);
        *(__nv_bfloat162*)&bcat_lo[rB] = split_lo2(u.x, u.y);
        const float v0 = u.x * sw[s], v1 = u.y * sw[s + 1];
        const size_t rU = ((size_t)bj * DINNER + pbase + p) * 128 + s;
        *(__nv_bfloat162*)&u2t_hi[rU] = split_hi2(v0, v1);
        *(__nv_bfloat162*)&u2t_lo[rU] = split_lo2(v0, v1);
    }
}

// ---------------------------------------------------------------------------
// bprep: B chunk transposed -> Bt2[n][s] hi/lo.
// ---------------------------------------------------------------------------
#define BPREP_SMEM (128 * 136 * 4)
__global__ void __launch_bounds__(256)
bprep(const float* __restrict__ xconv,
      __nv_bfloat16* __restrict__ bt2_hi, __nv_bfloat16* __restrict__ bt2_lo)
{
    extern __shared__ float sb[];
    const int bj  = blockIdx.x;
    const int tid = threadIdx.x;
    const int t0  = bj * CH;
    for (int idx = tid; idx < 128 * 128; idx += 256) {
        const int s = idx >> 7, n = idx & 127;
        sb[n * 136 + s] = xconv[(size_t)(t0 + s) * CONVCH + DINNER + n];
    }
    __syncthreads();
    for (int idx = tid; idx < 128 * 64; idx += 256) {
        const int n = idx >> 6, s2 = idx & 63, s = s2 * 2;
        const float2 v = *(const float2*)&sb[n * 136 + s];
        const size_t o = ((size_t)bj * DSTATE + n) * 128 + s;
        *(__nv_bfloat162*)&bt2_hi[o] = split_hi2(v.x, v.y);
        *(__nv_bfloat162*)&bt2_lo[o] = split_lo2(v.x, v.y);
    }
}

// ---------------------------------------------------------------------------
// state_scan: h recurrence over 16 chunks -> h_in into Bcat cols 128:256.
// ---------------------------------------------------------------------------
__global__ void __launch_bounds__(256)
state_scan(const float* __restrict__ S, const float* __restrict__ Dj,
           __nv_bfloat16* __restrict__ bcat_hi, __nv_bfloat16* __restrict__ bcat_lo)
{
    const int idx = blockIdx.x * 256 + threadIdx.x;
    const int b   = idx >> 16;
    const int rem = idx & 65535;
    const int p   = rem >> 6;
    const int n   = (rem & 63) * 2;
    float2 h = make_float2(0.f, 0.f);
#pragma unroll
    for (int j = 0; j < NCHUNK; j++) {
        const int bj = b * NCHUNK + j;
        const size_t row = ((size_t)bj * DINNER + p) * 256 + 128 + n;
        *(__nv_bfloat162*)&bcat_hi[row] = split_hi2(h.x, h.y);
        *(__nv_bfloat162*)&bcat_lo[row] = split_lo2(h.x, h.y);
        const float d = Dj[bj];
        const float2 sv = *(const float2*)&S[((size_t)bj << 17) + p * 128 + n];
        h.x = d * h.x + sv.x;
        h.y = d * h.y + sv.y;
    }
}

// ---------------------------------------------------------------------------
// y = (yraw + D*x) * silu(z); RMSNorm; emit yhi/ylo bf16 splits directly.
// ---------------------------------------------------------------------------
__global__ void gate_norm(const float* __restrict__ yraw,
                          const float* __restrict__ xconv,
                          const float* __restrict__ proj,
                          const float* __restrict__ normw,
                          const float* __restrict__ Dp,
                          __nv_bfloat16* __restrict__ yhi,
                          __nv_bfloat16* __restrict__ ylo)
{
    const int t   = blockIdx.x;
    const int tid = threadIdx.x;
    const float dval = Dp[0];

    float v[4];
    float ss = 0.f;
#pragma unroll
    for (int j = 0; j < 4; j++) {
        const int p = tid + j * 256;
        const float y = yraw[(size_t)t * DINNER + p]
                      + dval * xconv[(size_t)t * CONVCH + p];
        const float z = proj[(size_t)t * PLD + p];
        const float g = z / (1.f + expf(-z));
        const float val = y * g;
        v[j] = val;
        ss += val * val;
    }
#pragma unroll
    for (int m = 16; m; m >>= 1) ss += __shfl_xor_sync(0xffffffffu, ss, m);

    __shared__ float warpsum[8];
    __shared__ float inv_s;
    if ((tid & 31) == 0) warpsum[tid >> 5] = ss;
    __syncthreads();
    if (tid == 0) {
        float s = 0.f;
#pragma unroll
        for (int i = 0; i < 8; i++) s += warpsum[i];
        inv_s = rsqrtf(s * (1.f / DINNER) + 1e-5f);
    }
    __syncthreads();
    const float inv = inv_s;
#pragma unroll
    for (int j = 0; j < 4; j++) {
        const int p = tid + j * 256;
        const float val = v[j] * inv * normw[p];
        const __nv_bfloat16 h = __float2bfloat16(val);
        yhi[(size_t)t * DINNER + p] = h;
        ylo[(size_t)t * DINNER + p] = __float2bfloat16(val - __bfloat162float(h));
    }
}

// ---------------------------------------------------------------------------
extern "C" void kernel_launch(void* const* d_in, const int* in_sizes, int n_in,
                              void* d_out, int out_size)
{
    const float* x       = (const float*)d_in[0];
    const float* rnn     = (const float*)d_in[1];
    const float* W_in    = (const float*)d_in[2];
    const float* conv_w  = (const float*)d_in[3];
    const float* conv_b  = (const float*)d_in[4];
    const float* dt_bias = (const float*)d_in[5];
    const float* A_log   = (const float*)d_in[6];
    const float* Dp      = (const float*)d_in[7];
    const float* norm_w  = (const float*)d_in[8];
    const float* W_out   = (const float*)d_in[9];
    float* out = (float*)d_out;

    float *proj, *xconv, *gdt, *gla, *yraw, *sstate, *w1, *dj;
    __nv_bfloat16 *xhi, *xlo, *wihi, *wilo, *yhi, *ylo, *wohi, *wolo;
    __nv_bfloat16 *acat_hi, *acat_lo, *bcat_hi, *bcat_lo;
    __nv_bfloat16 *u2t_hi, *u2t_lo, *bt2_hi, *bt2_lo;
    cudaGetSymbolAddress((void**)&proj,    g_proj);
    cudaGetSymbolAddress((void**)&xconv,   g_xconv);
    cudaGetSymbolAddress((void**)&gdt,     g_dt);
    cudaGetSymbolAddress((void**)&gla,     g_la);
    cudaGetSymbolAddress((void**)&yraw,    g_yraw);
    cudaGetSymbolAddress((void**)&xhi,     g_xhi);
    cudaGetSymbolAddress((void**)&xlo,     g_xlo);
    cudaGetSymbolAddress((void**)&wihi,    g_wihi);
    cudaGetSymbolAddress((void**)&wilo,    g_wilo);
    cudaGetSymbolAddress((void**)&yhi,     g_yhi);
    cudaGetSymbolAddress((void**)&ylo,     g_ylo);
    cudaGetSymbolAddress((void**)&wohi,    g_wohi);
    cudaGetSymbolAddress((void**)&wolo,    g_wolo);
    cudaGetSymbolAddress((void**)&acat_hi, g_acat_hi);
    cudaGetSymbolAddress((void**)&acat_lo, g_acat_lo);
    cudaGetSymbolAddress((void**)&bcat_hi, g_bcat_hi);
    cudaGetSymbolAddress((void**)&bcat_lo, g_bcat_lo);
    cudaGetSymbolAddress((void**)&u2t_hi,  g_u2t_hi);
    cudaGetSymbolAddress((void**)&u2t_lo,  g_u2t_lo);
    cudaGetSymbolAddress((void**)&bt2_hi,  g_bt2_hi);
    cudaGetSymbolAddress((void**)&bt2_lo,  g_bt2_lo);
    cudaGetSymbolAddress((void**)&sstate,  g_sstate);
    cudaGetSymbolAddress((void**)&w1,      g_w1);
    cudaGetSymbolAddress((void**)&dj,      g_dj);

    cudaFuncSetAttribute(gemm_mma, cudaFuncAttributeMaxDynamicSharedMemorySize,
                         GEMM_SMEM);
    cudaFuncSetAttribute(chunk_prep, cudaFuncAttributeMaxDynamicSharedMemorySize,
                         S1_SMEM);
    cudaFuncSetAttribute(bprep, cudaFuncAttributeMaxDynamicSharedMemorySize,
                         BPREP_SMEM);

    // 0) bf16 splits of GEMM operands
    split_bf16<<<(TOK * DMODEL + 255) / 256, 256>>>(x, xhi, xlo, TOK * DMODEL);
    split_bf16<<<(NPROJ * DMODEL + 255) / 256, 256>>>(W_in, wihi, wilo, NPROJ * DMODEL);
    split_bf16<<<(DMODEL * DINNER + 255) / 256, 256>>>(W_out, wohi, wolo, DMODEL * DINNER);

    // 1) in-projection
    gemm_mma<<<dim3(NPROJ / 128, TOK / 128, 1), 256, GEMM_SMEM>>>(
        xhi, xlo, wihi, wilo, proj, DMODEL, PLD, 0, 0, 0);

    // 2) dt (exact fp32) + la
    dtprep<<<TOK / 8, 256>>>(x, W_in + (size_t)NPROJ * DMODEL, dt_bias, A_log, gdt, gla);

    // 3) conv + silu (sliding window)
    conv_silu<<<((TOK / 4) * CONVCH + 255) / 256, 256>>>(proj, conv_w, conv_b, xconv);

    // 4) chunked-SSD scan
    chunk_prep<<<BJ, 256, S1_SMEM>>>(xconv, gla, acat_hi, acat_lo, w1, dj);
    uprep<<<dim3(16, BJ), 256>>>(xconv, gdt, w1, bcat_hi, bcat_lo, u2t_hi, u2t_lo);
    bprep<<<BJ, 256, BPREP_SMEM>>>(xconv, bt2_hi, bt2_lo);
    gemm_mma<<<dim3(1, DINNER / 128, BJ), 256, GEMM_SMEM>>>(
        u2t_hi, u2t_lo, bt2_hi, bt2_lo, sstate, 128, DSTATE,
        (size_t)DINNER * 128, (size_t)DSTATE * 128, (size_t)DINNER * DSTATE);
    state_scan<<<1024, 256>>>(sstate, dj, bcat_hi, bcat_lo);
    gemm_mma<<<dim3(DINNER / 128, 1, BJ), 256, GEMM_SMEM>>>(
        acat_hi, acat_lo, bcat_hi, bcat_lo, yraw, 256, DINNER,
        (size_t)CH * 256, (size_t)DINNER * 256, (size_t)CH * DINNER);

    // 5) gate + RMSNorm, emitting bf16 hi/lo directly
    gate_norm<<<TOK, 256>>>(yraw, xconv, proj, norm_w, Dp, yhi, ylo);

    // 6) out-projection
    gemm_mma<<<dim3(DMODEL / 128, TOK / 128, 1), 256, GEMM_SMEM>>>(
        yhi, ylo, wohi, wolo, out, DINNER, DMODEL, 0, 0, 0);

    // 7) rnn_state passthrough
    const int main_elems = TOK * DMODEL;
    if (out_size >= main_elems + BATCH * DMODEL) {
        cudaMemcpyAsync(out + main_elems, rnn, (size_t)BATCH * DMODEL * sizeof(float),
                        cudaMemcpyDeviceToDevice, 0);
    }
}